// round 1
// baseline (speedup 1.0000x reference)
#include <cuda_runtime.h>
#include <math.h>

#define SEQ   4096
#define DIM   2048
#define NHEAD 16
#define HDIM  128
#define EPSF  1.1920929e-07f
#define ATT_SCALE 0.08838834764831845f  // 128^-0.5

// ---------------------------------------------------------------------------
// Scratch (device globals; allocation inside kernel_launch is forbidden)
// ---------------------------------------------------------------------------
__device__ float g_Q[SEQ * DIM];
__device__ float g_K[SEQ * DIM];
__device__ float g_V[SEQ * DIM];
__device__ float g_Y[SEQ * DIM];
__device__ float g_cos[SEQ * (HDIM / 2)];
__device__ float g_sin[SEQ * (HDIM / 2)];

// ---------------------------------------------------------------------------
// RoPE tables: inv_freq in double, angle rounded to fp32 (matches jax fp32
// outer product), cos/sin of that fp32 angle evaluated in double.
// ---------------------------------------------------------------------------
__global__ void build_rope_tables()
{
    int idx = blockIdx.x * blockDim.x + threadIdx.x;   // SEQ*64 threads
    int t = idx >> 6;
    int j = idx & 63;
    float invf = (float)pow(10000.0, -(double)j / 64.0);
    float ang = (float)t * invf;
    g_cos[idx] = (float)cos((double)ang);
    g_sin[idx] = (float)sin((double)ang);
}

// ---------------------------------------------------------------------------
// GEMM: C[M,N] = A[M,K] * B[N,K]^T, K = 2048, row-major, M,N multiples of 128.
// 128x128 tile, BK=16, 256 threads, 8x8 per thread.
// MODE 0: plain store. MODE 1: C = (1-lamb)*C + lamb*vi (fused v-mix).
// ---------------------------------------------------------------------------
template <int MODE>
__global__ __launch_bounds__(256, 2)
void gemm_nt(const float* __restrict__ A, const float* __restrict__ B,
             float* __restrict__ C,
             const float* __restrict__ vi, const float* __restrict__ lambp)
{
    __shared__ float As[16][128];
    __shared__ float Bs[16][128];

    const int tid = threadIdx.x;
    const int ldr = tid >> 2;          // 0..63
    const int ldk = (tid & 3) << 2;    // 0,4,8,12
    const int ty  = tid >> 4;          // 0..15
    const int tx  = tid & 15;          // 0..15

    const float* Ap = A + (blockIdx.y * 128 + ldr) * 2048 + ldk;
    const float* Bp = B + (blockIdx.x * 128 + ldr) * 2048 + ldk;

    float acc[8][8];
    #pragma unroll
    for (int i = 0; i < 8; i++)
        #pragma unroll
        for (int j = 0; j < 8; j++) acc[i][j] = 0.f;

    for (int k0 = 0; k0 < 2048; k0 += 16) {
        float4 a0 = *(const float4*)(Ap + k0);
        float4 a1 = *(const float4*)(Ap + 64 * 2048 + k0);
        float4 b0 = *(const float4*)(Bp + k0);
        float4 b1 = *(const float4*)(Bp + 64 * 2048 + k0);
        __syncthreads();
        As[ldk + 0][ldr]      = a0.x; As[ldk + 1][ldr]      = a0.y;
        As[ldk + 2][ldr]      = a0.z; As[ldk + 3][ldr]      = a0.w;
        As[ldk + 0][ldr + 64] = a1.x; As[ldk + 1][ldr + 64] = a1.y;
        As[ldk + 2][ldr + 64] = a1.z; As[ldk + 3][ldr + 64] = a1.w;
        Bs[ldk + 0][ldr]      = b0.x; Bs[ldk + 1][ldr]      = b0.y;
        Bs[ldk + 2][ldr]      = b0.z; Bs[ldk + 3][ldr]      = b0.w;
        Bs[ldk + 0][ldr + 64] = b1.x; Bs[ldk + 1][ldr + 64] = b1.y;
        Bs[ldk + 2][ldr + 64] = b1.z; Bs[ldk + 3][ldr + 64] = b1.w;
        __syncthreads();

        #pragma unroll
        for (int k = 0; k < 16; k++) {
            float4 af0 = *(const float4*)&As[k][ty * 8];
            float4 af1 = *(const float4*)&As[k][ty * 8 + 4];
            float4 bf0 = *(const float4*)&Bs[k][tx * 8];
            float4 bf1 = *(const float4*)&Bs[k][tx * 8 + 4];
            float a[8] = {af0.x, af0.y, af0.z, af0.w, af1.x, af1.y, af1.z, af1.w};
            float b[8] = {bf0.x, bf0.y, bf0.z, bf0.w, bf1.x, bf1.y, bf1.z, bf1.w};
            #pragma unroll
            for (int i = 0; i < 8; i++)
                #pragma unroll
                for (int j = 0; j < 8; j++)
                    acc[i][j] = fmaf(a[i], b[j], acc[i][j]);
        }
    }

    const int r0 = blockIdx.y * 128 + ty * 8;
    const int c0 = blockIdx.x * 128 + tx * 8;
    float lam = 0.f, oml = 1.f;
    if (MODE == 1) { lam = *lambp; oml = 1.f - lam; }

    #pragma unroll
    for (int i = 0; i < 8; i++) {
        float* Cp = C + (r0 + i) * 2048 + c0;
        if (MODE == 1) {
            const float4 v0 = *(const float4*)(vi + (r0 + i) * 2048 + c0);
            const float4 v1 = *(const float4*)(vi + (r0 + i) * 2048 + c0 + 4);
            float4 w0 = make_float4(oml * acc[i][0] + lam * v0.x,
                                    oml * acc[i][1] + lam * v0.y,
                                    oml * acc[i][2] + lam * v0.z,
                                    oml * acc[i][3] + lam * v0.w);
            float4 w1 = make_float4(oml * acc[i][4] + lam * v1.x,
                                    oml * acc[i][5] + lam * v1.y,
                                    oml * acc[i][6] + lam * v1.z,
                                    oml * acc[i][7] + lam * v1.w);
            *(float4*)(Cp)     = w0;
            *(float4*)(Cp + 4) = w1;
        } else {
            *(float4*)(Cp)     = make_float4(acc[i][0], acc[i][1], acc[i][2], acc[i][3]);
            *(float4*)(Cp + 4) = make_float4(acc[i][4], acc[i][5], acc[i][6], acc[i][7]);
        }
    }
}

// ---------------------------------------------------------------------------
// Fused RMSNorm + RoPE, in-place on Q (z=0) and K (z=1).
// One block per (t, head), 128 threads.
// ---------------------------------------------------------------------------
__global__ void rmsnorm_rope(float* __restrict__ Q, float* __restrict__ K)
{
    const int t = blockIdx.x;
    const int h = blockIdx.y;
    float* row = (blockIdx.z == 0 ? Q : K) + t * 2048 + h * 128;
    const int i = threadIdx.x;    // 0..127

    float v = row[i];
    float ss = v * v;
    #pragma unroll
    for (int o = 16; o > 0; o >>= 1) ss += __shfl_xor_sync(0xffffffffu, ss, o);

    __shared__ float red[4];
    __shared__ float vals[128];
    if ((i & 31) == 0) red[i >> 5] = ss;
    __syncthreads();
    float tot = red[0] + red[1] + red[2] + red[3];
    float nv = v * rsqrtf(tot * (1.f / 128.f) + EPSF);
    vals[i] = nv;
    __syncthreads();

    if (i < 64) {
        float x1 = vals[i], x2 = vals[i + 64];
        float c = g_cos[t * 64 + i];
        float s = g_sin[t * 64 + i];
        row[i]      = x1 * c + x2 * s;
        row[i + 64] = x2 * c - x1 * s;
    }
}

// ---------------------------------------------------------------------------
// Causal flash attention, fp32. Block = (64 queries, 1 head), 256 threads.
// Q/K stored transposed in smem ([d][row], pad 68) for float4 fragment loads;
// V natural ([c][d], pad 132); P transposed ([c][r], pad 68) for the PV gemm.
// ---------------------------------------------------------------------------
#define FL_SMEM_FLOATS (2 * 128 * 68 + 64 * 132 + 64 * 68)
#define FL_SMEM_BYTES  (FL_SMEM_FLOATS * 4)

__global__ __launch_bounds__(256, 1)
void flash_attn()
{
    extern __shared__ float sm[];
    float* Qt = sm;                               // [128][68]
    float* Kt = sm + 128 * 68;                    // [128][68]
    float* Vs = sm + 2 * 128 * 68;                // [64][132]
    float* Pt = sm + 2 * 128 * 68 + 64 * 132;     // [64][68]

    const int qb  = blockIdx.x;
    const int h   = blockIdx.y;
    const int tid = threadIdx.x;
    const int ty  = tid >> 4;   // 0..15 -> rows ty*4..ty*4+3
    const int tx  = tid & 15;   // 0..15 -> S cols tx*4..+3, O cols tx*8..+7
    const int q0  = qb * 64;

    for (int idx = tid; idx < 64 * 128; idx += 256) {
        int r = idx >> 7, d = idx & 127;
        Qt[d * 68 + r] = g_Q[(q0 + r) * 2048 + h * 128 + d];
    }
    __syncthreads();

    float m[4], l[4], o[4][8];
    #pragma unroll
    for (int i = 0; i < 4; i++) {
        m[i] = -1e30f; l[i] = 0.f;
        #pragma unroll
        for (int j = 0; j < 8; j++) o[i][j] = 0.f;
    }

    for (int kb = 0; kb <= qb; kb++) {
        const int k0 = kb * 64;
        for (int idx = tid; idx < 64 * 128; idx += 256) {
            int c = idx >> 7, d = idx & 127;
            Kt[d * 68 + c]  = g_K[(k0 + c) * 2048 + h * 128 + d];
            Vs[c * 132 + d] = g_V[(k0 + c) * 2048 + h * 128 + d];
        }
        __syncthreads();

        // S = Q K^T (64x64), each thread a 4x4 tile
        float s[4][4];
        #pragma unroll
        for (int i = 0; i < 4; i++)
            #pragma unroll
            for (int j = 0; j < 4; j++) s[i][j] = 0.f;

        #pragma unroll 8
        for (int d = 0; d < 128; d++) {
            float4 qf = *(const float4*)&Qt[d * 68 + ty * 4];
            float4 kf = *(const float4*)&Kt[d * 68 + tx * 4];
            float qa[4] = {qf.x, qf.y, qf.z, qf.w};
            float ka[4] = {kf.x, kf.y, kf.z, kf.w};
            #pragma unroll
            for (int i = 0; i < 4; i++)
                #pragma unroll
                for (int j = 0; j < 4; j++)
                    s[i][j] = fmaf(qa[i], ka[j], s[i][j]);
        }

        const bool diag = (kb == qb);
        #pragma unroll
        for (int i = 0; i < 4; i++)
            #pragma unroll
            for (int j = 0; j < 4; j++) {
                s[i][j] *= ATT_SCALE;
                if (diag && (k0 + tx * 4 + j > q0 + ty * 4 + i)) s[i][j] = -1e30f;
            }

        // online softmax: stats reduced across the 16 threads sharing a row
        float mb[4];
        #pragma unroll
        for (int i = 0; i < 4; i++) {
            mb[i] = fmaxf(fmaxf(s[i][0], s[i][1]), fmaxf(s[i][2], s[i][3]));
            #pragma unroll
            for (int off = 8; off > 0; off >>= 1)
                mb[i] = fmaxf(mb[i], __shfl_xor_sync(0xffffffffu, mb[i], off));
        }
        float al[4];
        #pragma unroll
        for (int i = 0; i < 4; i++) {
            float mn = fmaxf(m[i], mb[i]);
            al[i] = __expf(m[i] - mn);
            m[i] = mn;
        }
        float p[4][4], rs[4];
        #pragma unroll
        for (int i = 0; i < 4; i++) {
            #pragma unroll
            for (int j = 0; j < 4; j++) p[i][j] = __expf(s[i][j] - m[i]);
            rs[i] = p[i][0] + p[i][1] + p[i][2] + p[i][3];
            #pragma unroll
            for (int off = 8; off > 0; off >>= 1)
                rs[i] += __shfl_xor_sync(0xffffffffu, rs[i], off);
            l[i] = l[i] * al[i] + rs[i];
            #pragma unroll
            for (int j = 0; j < 8; j++) o[i][j] *= al[i];
        }

        // P -> smem transposed [c][r]
        #pragma unroll
        for (int j = 0; j < 4; j++) {
            float4 pv = make_float4(p[0][j], p[1][j], p[2][j], p[3][j]);
            *(float4*)&Pt[(tx * 4 + j) * 68 + ty * 4] = pv;
        }
        __syncthreads();

        // O += P V  (contraction over 64 keys)
        #pragma unroll 4
        for (int c = 0; c < 64; c++) {
            float4 pf = *(const float4*)&Pt[c * 68 + ty * 4];
            float4 v0 = *(const float4*)&Vs[c * 132 + tx * 8];
            float4 v1 = *(const float4*)&Vs[c * 132 + tx * 8 + 4];
            float pa[4] = {pf.x, pf.y, pf.z, pf.w};
            float va[8] = {v0.x, v0.y, v0.z, v0.w, v1.x, v1.y, v1.z, v1.w};
            #pragma unroll
            for (int i = 0; i < 4; i++)
                #pragma unroll
                for (int j = 0; j < 8; j++)
                    o[i][j] = fmaf(pa[i], va[j], o[i][j]);
        }
        __syncthreads();
    }

    #pragma unroll
    for (int i = 0; i < 4; i++) {
        float inv = 1.f / l[i];
        int row = q0 + ty * 4 + i;
        float* yp = g_Y + row * 2048 + h * 128 + tx * 8;
        *(float4*)(yp)     = make_float4(o[i][0] * inv, o[i][1] * inv,
                                         o[i][2] * inv, o[i][3] * inv);
        *(float4*)(yp + 4) = make_float4(o[i][4] * inv, o[i][5] * inv,
                                         o[i][6] * inv, o[i][7] * inv);
    }
}

// ---------------------------------------------------------------------------
// Launch
// ---------------------------------------------------------------------------
extern "C" void kernel_launch(void* const* d_in, const int* in_sizes, int n_in,
                              void* d_out, int out_size)
{
    (void)in_sizes; (void)n_in; (void)out_size;
    const float* x    = (const float*)d_in[0];
    const float* vi   = (const float*)d_in[1];
    const float* Wq   = (const float*)d_in[2];
    const float* Wk   = (const float*)d_in[3];
    const float* Wv   = (const float*)d_in[4];
    const float* Wp   = (const float*)d_in[5];
    const float* lamb = (const float*)d_in[6];
    float* out = (float*)d_out;

    float *Qp, *Kp, *Vp, *Yp;
    cudaGetSymbolAddress((void**)&Qp, g_Q);
    cudaGetSymbolAddress((void**)&Kp, g_K);
    cudaGetSymbolAddress((void**)&Vp, g_V);
    cudaGetSymbolAddress((void**)&Yp, g_Y);

    build_rope_tables<<<(SEQ * 64) / 256, 256>>>();

    dim3 gg(DIM / 128, SEQ / 128);
    gemm_nt<0><<<gg, 256>>>(x, Wq, Qp, nullptr, nullptr);
    gemm_nt<0><<<gg, 256>>>(x, Wk, Kp, nullptr, nullptr);
    gemm_nt<1><<<gg, 256>>>(x, Wv, Vp, vi, lamb);

    rmsnorm_rope<<<dim3(SEQ, NHEAD, 2), 128>>>(Qp, Kp);

    cudaFuncSetAttribute(flash_attn,
                         cudaFuncAttributeMaxDynamicSharedMemorySize,
                         FL_SMEM_BYTES);
    flash_attn<<<dim3(SEQ / 64, NHEAD), 256, FL_SMEM_BYTES>>>();

    gemm_nt<0><<<gg, 256>>>(Yp, Wp, out, nullptr, nullptr);
}

// round 5
// speedup vs baseline: 1.5703x; 1.5703x over previous
#include <cuda_runtime.h>
#include <cuda_bf16.h>
#include <math.h>
#include <stdint.h>

#define SEQ   4096
#define DIM   2048
#define NHEAD 16
#define HDIM  128
#define EPSF  1.1920929e-07f
#define ATT_SCALE 0.08838834764831845f  // 128^-0.5

#define SW128(o) ((o) ^ (((o) >> 3) & 0x70))

// ---------------------------------------------------------------------------
// Scratch (device globals; no allocation allowed)
// ---------------------------------------------------------------------------
__device__ float g_Q[SEQ * DIM];
__device__ float g_K[SEQ * DIM];
__device__ float g_V[SEQ * DIM];
__device__ float g_cos[SEQ * (HDIM / 2)];
__device__ float g_sin[SEQ * (HDIM / 2)];
__device__ __nv_bfloat16 g_Xhi[SEQ * DIM];
__device__ __nv_bfloat16 g_Xlo[SEQ * DIM];
__device__ __nv_bfloat16 g_Yhi[SEQ * DIM];
__device__ __nv_bfloat16 g_Ylo[SEQ * DIM];
__device__ __nv_bfloat16 g_Whi[4 * DIM * DIM];   // Wq, Wk, Wv, Wproj
__device__ __nv_bfloat16 g_Wlo[4 * DIM * DIM];

// ---------------------------------------------------------------------------
// PTX helpers (all baseline sm_80+ — target is plain sm_100, no 'a' features)
// ---------------------------------------------------------------------------
__device__ __forceinline__ uint32_t smem_u32(const void* p) {
    uint32_t a;
    asm("{ .reg .u64 t; cvta.to.shared.u64 t, %1; cvt.u32.u64 %0, t; }"
        : "=r"(a) : "l"(p));
    return a;
}

__device__ __forceinline__ void cp16(uint32_t dst, const void* src) {
    asm volatile("cp.async.cg.shared.global [%0], [%1], 16;"
                 :: "r"(dst), "l"(src) : "memory");
}
__device__ __forceinline__ void cp_commit() {
    asm volatile("cp.async.commit_group;" ::: "memory");
}
template <int N>
__device__ __forceinline__ void cp_wait() {
    asm volatile("cp.async.wait_group %0;" :: "n"(N) : "memory");
}

__device__ __forceinline__ void ldsm4(uint32_t& r0, uint32_t& r1,
                                      uint32_t& r2, uint32_t& r3, uint32_t a) {
    asm volatile("ldmatrix.sync.aligned.m8n8.x4.shared.b16 {%0,%1,%2,%3}, [%4];"
                 : "=r"(r0), "=r"(r1), "=r"(r2), "=r"(r3) : "r"(a));
}
// B stored [n][k] (k contiguous) == col-major k x n: NON-transposed ldmatrix
// yields b0 = B[n=t/4][k=2(t%4)+j] which is exactly the m16n8k16 B fragment.
__device__ __forceinline__ void ldsm2(uint32_t& r0, uint32_t& r1, uint32_t a) {
    asm volatile("ldmatrix.sync.aligned.m8n8.x2.shared.b16 {%0,%1}, [%2];"
                 : "=r"(r0), "=r"(r1) : "r"(a));
}
__device__ __forceinline__ void mma16816(float* c, const uint32_t* a,
                                         const uint32_t* b) {
    asm volatile(
        "mma.sync.aligned.m16n8k16.row.col.f32.bf16.bf16.f32 "
        "{%0,%1,%2,%3}, {%4,%5,%6,%7}, {%8,%9}, {%0,%1,%2,%3};"
        : "+f"(c[0]), "+f"(c[1]), "+f"(c[2]), "+f"(c[3])
        : "r"(a[0]), "r"(a[1]), "r"(a[2]), "r"(a[3]), "r"(b[0]), "r"(b[1]));
}

// ---------------------------------------------------------------------------
// RoPE tables
// ---------------------------------------------------------------------------
__global__ void build_rope_tables()
{
    int idx = blockIdx.x * blockDim.x + threadIdx.x;
    int t = idx >> 6;
    int j = idx & 63;
    float invf = (float)pow(10000.0, -(double)j / 64.0);
    float ang = (float)t * invf;
    g_cos[idx] = (float)cos((double)ang);
    g_sin[idx] = (float)sin((double)ang);
}

// ---------------------------------------------------------------------------
// fp32 -> (bf16 hi, bf16 lo) split
// ---------------------------------------------------------------------------
__global__ void split_bf16(const float4* __restrict__ src,
                           __nv_bfloat162* __restrict__ hi,
                           __nv_bfloat162* __restrict__ lo)
{
    int i = blockIdx.x * blockDim.x + threadIdx.x;
    float4 v = src[i];
    __nv_bfloat162 h0 = __floats2bfloat162_rn(v.x, v.y);
    __nv_bfloat162 h1 = __floats2bfloat162_rn(v.z, v.w);
    __nv_bfloat162 l0 = __floats2bfloat162_rn(v.x - __bfloat162float(h0.x),
                                              v.y - __bfloat162float(h0.y));
    __nv_bfloat162 l1 = __floats2bfloat162_rn(v.z - __bfloat162float(h1.x),
                                              v.w - __bfloat162float(h1.y));
    hi[2 * i] = h0; hi[2 * i + 1] = h1;
    lo[2 * i] = l0; lo[2 * i + 1] = l1;
}

// ---------------------------------------------------------------------------
// mma.sync GEMM: C[M,N] = A[M,K]*B[N,K]^T, 3-term bf16 split.
// CTA 128x128, BK=64, 256 threads (8 warps, warp tile 64x32),
// cp.async double buffer, SW128-swizzled smem (128B rows).
// MODE 1 fuses C = (1-lamb)*C + lamb*vi.
// ---------------------------------------------------------------------------
#define OPND 16384                       // one operand tile: 128x64 bf16
#define STAGE (4 * OPND)                 // Ah, Al, Bh, Bl
#define GM_SMEM (2 * STAGE)              // 131072 B

template <int MODE>
__global__ __launch_bounds__(256, 1)
void gemm_mma(const __nv_bfloat16* __restrict__ Ahi, const __nv_bfloat16* __restrict__ Alo,
              const __nv_bfloat16* __restrict__ Bhi, const __nv_bfloat16* __restrict__ Blo,
              float* __restrict__ C,
              const float* __restrict__ vi, const float* __restrict__ lambp)
{
    extern __shared__ char smc[];
    const uint32_t sb = smem_u32(smc);
    const int tid = threadIdx.x;
    const int wid = tid >> 5;
    const int lid = tid & 31;
    const int warp_m = wid & 1;          // 0..1 -> 64-row slab
    const int warp_n = wid >> 1;         // 0..3 -> 32-col slab
    const int m0 = blockIdx.y * 128;
    const int n0 = blockIdx.x * 128;

    const __nv_bfloat16* srcs[4] = { Ahi + (size_t)m0 * DIM, Alo + (size_t)m0 * DIM,
                                     Bhi + (size_t)n0 * DIM, Blo + (size_t)n0 * DIM };

    // cp.async indexing: thread covers 4 16B-units per operand
    const int ldrow = tid >> 3;          // 0..31 (row base; +32 per q)
    const int ldu   = tid & 7;           // 16B unit 0..7 within 128B row

    auto load_chunk = [&](int chunk, int stage) {
        const int k0 = chunk * 64;
        #pragma unroll
        for (int t = 0; t < 4; t++) {
            const __nv_bfloat16* s = srcs[t] + k0 + ldu * 8;
            uint32_t dbase = sb + stage * STAGE + t * OPND;
            #pragma unroll
            for (int q = 0; q < 4; q++) {
                int row = ldrow + q * 32;
                cp16(dbase + SW128((uint32_t)(row * 128 + ldu * 16)),
                     s + (size_t)row * DIM);
            }
        }
        cp_commit();
    };

    float acc[4][4][4];
    #pragma unroll
    for (int a = 0; a < 4; a++)
        #pragma unroll
        for (int b = 0; b < 4; b++)
            #pragma unroll
            for (int c = 0; c < 4; c++) acc[a][b][c] = 0.f;

    // precomputed ldmatrix lane offsets (row part only; k-unit added per step)
    const int aq = lid >> 3;                                   // 0..3
    const int a_row = warp_m * 64 + (aq & 1) * 8 + (lid & 7);  // + mt*16
    const int a_ku  = aq >> 1;                                 // 0/1 extra 16B
    const int b_row = warp_n * 32 + (lid & 7);                 // + nt*8
    const int b_ku  = (lid >> 3) & 1;

    load_chunk(0, 0);

    for (int i = 0; i < 32; i++) {
        if (i + 1 < 32) { load_chunk(i + 1, (i + 1) & 1); cp_wait<1>(); }
        else            { cp_wait<0>(); }
        __syncthreads();

        const uint32_t st = sb + (i & 1) * STAGE;
        const uint32_t bAh = st, bAl = st + OPND, bBh = st + 2 * OPND, bBl = st + 3 * OPND;

        #pragma unroll
        for (int ks = 0; ks < 4; ks++) {
            uint32_t bh[8], bl[8];
            #pragma unroll
            for (int nt = 0; nt < 4; nt++) {
                uint32_t off = SW128((uint32_t)((b_row + nt * 8) * 128 + (ks * 2 + b_ku) * 16));
                ldsm2(bh[nt * 2], bh[nt * 2 + 1], bBh + off);
                ldsm2(bl[nt * 2], bl[nt * 2 + 1], bBl + off);
            }
            #pragma unroll
            for (int mt = 0; mt < 4; mt++) {
                uint32_t off = SW128((uint32_t)((a_row + mt * 16) * 128 + (ks * 2 + a_ku) * 16));
                uint32_t ah[4], al[4];
                ldsm4(ah[0], ah[1], ah[2], ah[3], bAh + off);
                ldsm4(al[0], al[1], al[2], al[3], bAl + off);
                #pragma unroll
                for (int nt = 0; nt < 4; nt++) {
                    mma16816(acc[mt][nt], ah, &bh[nt * 2]);
                    mma16816(acc[mt][nt], ah, &bl[nt * 2]);
                    mma16816(acc[mt][nt], al, &bh[nt * 2]);
                }
            }
        }
        __syncthreads();
    }

    // epilogue
    float lam = 0.f, oml = 1.f;
    if (MODE == 1) { lam = *lambp; oml = 1.f - lam; }
    const int gid = lid >> 2;            // groupID 0..7
    const int tg  = lid & 3;
    #pragma unroll
    for (int mt = 0; mt < 4; mt++) {
        #pragma unroll
        for (int nt = 0; nt < 4; nt++) {
            int r = m0 + warp_m * 64 + mt * 16 + gid;
            int c = n0 + warp_n * 32 + nt * 8 + tg * 2;
            float2 v01 = make_float2(acc[mt][nt][0], acc[mt][nt][1]);
            float2 v23 = make_float2(acc[mt][nt][2], acc[mt][nt][3]);
            if (MODE == 1) {
                float2 w0 = *(const float2*)(vi + (size_t)r * DIM + c);
                float2 w1 = *(const float2*)(vi + (size_t)(r + 8) * DIM + c);
                v01.x = oml * v01.x + lam * w0.x; v01.y = oml * v01.y + lam * w0.y;
                v23.x = oml * v23.x + lam * w1.x; v23.y = oml * v23.y + lam * w1.y;
            }
            *(float2*)(C + (size_t)r * DIM + c) = v01;
            *(float2*)(C + (size_t)(r + 8) * DIM + c) = v23;
        }
    }
}

// ---------------------------------------------------------------------------
// Fused RMSNorm + RoPE
// ---------------------------------------------------------------------------
__global__ void rmsnorm_rope(float* __restrict__ Q, float* __restrict__ K)
{
    const int t = blockIdx.x;
    const int h = blockIdx.y;
    float* row = (blockIdx.z == 0 ? Q : K) + t * 2048 + h * 128;
    const int i = threadIdx.x;

    float v = row[i];
    float ss = v * v;
    #pragma unroll
    for (int o = 16; o > 0; o >>= 1) ss += __shfl_xor_sync(0xffffffffu, ss, o);

    __shared__ float red[4];
    __shared__ float vals[128];
    if ((i & 31) == 0) red[i >> 5] = ss;
    __syncthreads();
    float tot = red[0] + red[1] + red[2] + red[3];
    float nv = v * rsqrtf(tot * (1.f / 128.f) + EPSF);
    vals[i] = nv;
    __syncthreads();

    if (i < 64) {
        float x1 = vals[i], x2 = vals[i + 64];
        float c = g_cos[t * 64 + i];
        float s = g_sin[t * 64 + i];
        row[i]      = x1 * c + x2 * s;
        row[i + 64] = x2 * c - x1 * s;
    }
}

// ---------------------------------------------------------------------------
// Causal flash attention (fp32 SIMT), epilogue writes bf16 hi/lo of Y.
// ---------------------------------------------------------------------------
#define FL_SMEM_FLOATS (2 * 128 * 68 + 64 * 132 + 64 * 68)
#define FL_SMEM_BYTES  (FL_SMEM_FLOATS * 4)

__global__ __launch_bounds__(256, 1)
void flash_attn()
{
    extern __shared__ float sm[];
    float* Qt = sm;                               // [128][68]
    float* Kt = sm + 128 * 68;                    // [128][68]
    float* Vs = sm + 2 * 128 * 68;                // [64][132]
    float* Pt = sm + 2 * 128 * 68 + 64 * 132;     // [64][68]

    const int qb  = blockIdx.x;
    const int h   = blockIdx.y;
    const int tid = threadIdx.x;
    const int ty  = tid >> 4;
    const int tx  = tid & 15;
    const int q0  = qb * 64;

    for (int idx = tid; idx < 64 * 128; idx += 256) {
        int r = idx >> 7, d = idx & 127;
        Qt[d * 68 + r] = g_Q[(q0 + r) * 2048 + h * 128 + d];
    }
    __syncthreads();

    float m[4], l[4], o[4][8];
    #pragma unroll
    for (int i = 0; i < 4; i++) {
        m[i] = -1e30f; l[i] = 0.f;
        #pragma unroll
        for (int j = 0; j < 8; j++) o[i][j] = 0.f;
    }

    for (int kb = 0; kb <= qb; kb++) {
        const int k0 = kb * 64;
        for (int idx = tid; idx < 64 * 128; idx += 256) {
            int c = idx >> 7, d = idx & 127;
            Kt[d * 68 + c]  = g_K[(k0 + c) * 2048 + h * 128 + d];
            Vs[c * 132 + d] = g_V[(k0 + c) * 2048 + h * 128 + d];
        }
        __syncthreads();

        float s[4][4];
        #pragma unroll
        for (int i = 0; i < 4; i++)
            #pragma unroll
            for (int j = 0; j < 4; j++) s[i][j] = 0.f;

        #pragma unroll 8
        for (int d = 0; d < 128; d++) {
            float4 qf = *(const float4*)&Qt[d * 68 + ty * 4];
            float4 kf = *(const float4*)&Kt[d * 68 + tx * 4];
            float qa[4] = {qf.x, qf.y, qf.z, qf.w};
            float ka[4] = {kf.x, kf.y, kf.z, kf.w};
            #pragma unroll
            for (int i = 0; i < 4; i++)
                #pragma unroll
                for (int j = 0; j < 4; j++)
                    s[i][j] = fmaf(qa[i], ka[j], s[i][j]);
        }

        const bool diag = (kb == qb);
        #pragma unroll
        for (int i = 0; i < 4; i++)
            #pragma unroll
            for (int j = 0; j < 4; j++) {
                s[i][j] *= ATT_SCALE;
                if (diag && (k0 + tx * 4 + j > q0 + ty * 4 + i)) s[i][j] = -1e30f;
            }

        float mb[4];
        #pragma unroll
        for (int i = 0; i < 4; i++) {
            mb[i] = fmaxf(fmaxf(s[i][0], s[i][1]), fmaxf(s[i][2], s[i][3]));
            #pragma unroll
            for (int off = 8; off > 0; off >>= 1)
                mb[i] = fmaxf(mb[i], __shfl_xor_sync(0xffffffffu, mb[i], off));
        }
        float al[4];
        #pragma unroll
        for (int i = 0; i < 4; i++) {
            float mn = fmaxf(m[i], mb[i]);
            al[i] = __expf(m[i] - mn);
            m[i] = mn;
        }
        float p[4][4], rs[4];
        #pragma unroll
        for (int i = 0; i < 4; i++) {
            #pragma unroll
            for (int j = 0; j < 4; j++) p[i][j] = __expf(s[i][j] - m[i]);
            rs[i] = p[i][0] + p[i][1] + p[i][2] + p[i][3];
            #pragma unroll
            for (int off = 8; off > 0; off >>= 1)
                rs[i] += __shfl_xor_sync(0xffffffffu, rs[i], off);
            l[i] = l[i] * al[i] + rs[i];
            #pragma unroll
            for (int j = 0; j < 8; j++) o[i][j] *= al[i];
        }

        #pragma unroll
        for (int j = 0; j < 4; j++) {
            float4 pv = make_float4(p[0][j], p[1][j], p[2][j], p[3][j]);
            *(float4*)&Pt[(tx * 4 + j) * 68 + ty * 4] = pv;
        }
        __syncthreads();

        #pragma unroll 4
        for (int c = 0; c < 64; c++) {
            float4 pf = *(const float4*)&Pt[c * 68 + ty * 4];
            float4 v0 = *(const float4*)&Vs[c * 132 + tx * 8];
            float4 v1 = *(const float4*)&Vs[c * 132 + tx * 8 + 4];
            float pa[4] = {pf.x, pf.y, pf.z, pf.w};
            float va[8] = {v0.x, v0.y, v0.z, v0.w, v1.x, v1.y, v1.z, v1.w};
            #pragma unroll
            for (int i = 0; i < 4; i++)
                #pragma unroll
                for (int j = 0; j < 8; j++)
                    o[i][j] = fmaf(pa[i], va[j], o[i][j]);
        }
        __syncthreads();
    }

    // epilogue: write Y as bf16 hi/lo (feeds proj GEMM)
    #pragma unroll
    for (int i = 0; i < 4; i++) {
        float inv = 1.f / l[i];
        int row = q0 + ty * 4 + i;
        int base = row * 2048 + h * 128 + tx * 8;
        __nv_bfloat162* yh = (__nv_bfloat162*)(g_Yhi + base);
        __nv_bfloat162* yl = (__nv_bfloat162*)(g_Ylo + base);
        #pragma unroll
        for (int jj = 0; jj < 4; jj++) {
            float a = o[i][2 * jj] * inv;
            float b = o[i][2 * jj + 1] * inv;
            __nv_bfloat162 hh = __floats2bfloat162_rn(a, b);
            __nv_bfloat162 ll = __floats2bfloat162_rn(a - __bfloat162float(hh.x),
                                                      b - __bfloat162float(hh.y));
            yh[jj] = hh;
            yl[jj] = ll;
        }
    }
}

// ---------------------------------------------------------------------------
// Launch
// ---------------------------------------------------------------------------
extern "C" void kernel_launch(void* const* d_in, const int* in_sizes, int n_in,
                              void* d_out, int out_size)
{
    (void)in_sizes; (void)n_in; (void)out_size;
    const float* x    = (const float*)d_in[0];
    const float* vi   = (const float*)d_in[1];
    const float* Wq   = (const float*)d_in[2];
    const float* Wk   = (const float*)d_in[3];
    const float* Wv   = (const float*)d_in[4];
    const float* Wp   = (const float*)d_in[5];
    const float* lamb = (const float*)d_in[6];
    float* out = (float*)d_out;

    float *Qp, *Kp, *Vp;
    __nv_bfloat16 *Xhi, *Xlo, *Yhi, *Ylo, *Whi, *Wlo;
    cudaGetSymbolAddress((void**)&Qp, g_Q);
    cudaGetSymbolAddress((void**)&Kp, g_K);
    cudaGetSymbolAddress((void**)&Vp, g_V);
    cudaGetSymbolAddress((void**)&Xhi, g_Xhi);
    cudaGetSymbolAddress((void**)&Xlo, g_Xlo);
    cudaGetSymbolAddress((void**)&Yhi, g_Yhi);
    cudaGetSymbolAddress((void**)&Ylo, g_Ylo);
    cudaGetSymbolAddress((void**)&Whi, g_Whi);
    cudaGetSymbolAddress((void**)&Wlo, g_Wlo);

    build_rope_tables<<<(SEQ * 64) / 256, 256>>>();

    split_bf16<<<(SEQ * DIM / 4) / 256, 256>>>((const float4*)x,
        (__nv_bfloat162*)Xhi, (__nv_bfloat162*)Xlo);
    const float* Ws[4] = {Wq, Wk, Wv, Wp};
    for (int w = 0; w < 4; w++) {
        split_bf16<<<(DIM * DIM / 4) / 256, 256>>>((const float4*)Ws[w],
            (__nv_bfloat162*)(Whi + (size_t)w * DIM * DIM),
            (__nv_bfloat162*)(Wlo + (size_t)w * DIM * DIM));
    }

    cudaFuncSetAttribute(gemm_mma<0>, cudaFuncAttributeMaxDynamicSharedMemorySize, GM_SMEM);
    cudaFuncSetAttribute(gemm_mma<1>, cudaFuncAttributeMaxDynamicSharedMemorySize, GM_SMEM);

    dim3 gg(DIM / 128, SEQ / 128);
    gemm_mma<0><<<gg, 256, GM_SMEM>>>(Xhi, Xlo,
        Whi + 0 * (size_t)DIM * DIM, Wlo + 0 * (size_t)DIM * DIM, Qp, nullptr, nullptr);
    gemm_mma<0><<<gg, 256, GM_SMEM>>>(Xhi, Xlo,
        Whi + 1 * (size_t)DIM * DIM, Wlo + 1 * (size_t)DIM * DIM, Kp, nullptr, nullptr);
    gemm_mma<1><<<gg, 256, GM_SMEM>>>(Xhi, Xlo,
        Whi + 2 * (size_t)DIM * DIM, Wlo + 2 * (size_t)DIM * DIM, Vp, vi, lamb);

    rmsnorm_rope<<<dim3(SEQ, NHEAD, 2), 128>>>(Qp, Kp);

    cudaFuncSetAttribute(flash_attn,
                         cudaFuncAttributeMaxDynamicSharedMemorySize, FL_SMEM_BYTES);
    flash_attn<<<dim3(SEQ / 64, NHEAD), 256, FL_SMEM_BYTES>>>();

    gemm_mma<0><<<gg, 256, GM_SMEM>>>(Yhi, Ylo,
        Whi + 3 * (size_t)DIM * DIM, Wlo + 3 * (size_t)DIM * DIM, out, nullptr, nullptr);
}

// round 6
// speedup vs baseline: 1.5707x; 1.0003x over previous
#include <cuda_runtime.h>
#include <cuda_bf16.h>
#include <math.h>
#include <stdint.h>

#define SEQ   4096
#define DIM   2048
#define NHEAD 16
#define HDIM  128
#define EPSF  1.1920929e-07f
#define ATT_SCALE 0.08838834764831845f  // 128^-0.5

#define SW128(o) ((o) ^ (((o) >> 3) & 0x70))

// ---------------------------------------------------------------------------
// Scratch (device globals; no allocation allowed)
// ---------------------------------------------------------------------------
__device__ float g_Q[SEQ * DIM];
__device__ float g_K[SEQ * DIM];
__device__ float g_V[SEQ * DIM];
__device__ float g_cos[SEQ * (HDIM / 2)];
__device__ float g_sin[SEQ * (HDIM / 2)];
__device__ __nv_bfloat16 g_Xhi[SEQ * DIM];
__device__ __nv_bfloat16 g_Xlo[SEQ * DIM];
__device__ __nv_bfloat16 g_Yhi[SEQ * DIM];
__device__ __nv_bfloat16 g_Ylo[SEQ * DIM];
__device__ __nv_bfloat16 g_Whi[4 * DIM * DIM];   // Wq, Wk, Wv, Wproj
__device__ __nv_bfloat16 g_Wlo[4 * DIM * DIM];

// ---------------------------------------------------------------------------
// PTX helpers (all baseline sm_80+ — target is plain sm_100, no 'a' features)
// ---------------------------------------------------------------------------
__device__ __forceinline__ uint32_t smem_u32(const void* p) {
    uint32_t a;
    asm("{ .reg .u64 t; cvta.to.shared.u64 t, %1; cvt.u32.u64 %0, t; }"
        : "=r"(a) : "l"(p));
    return a;
}

__device__ __forceinline__ void cp16(uint32_t dst, const void* src) {
    asm volatile("cp.async.cg.shared.global [%0], [%1], 16;"
                 :: "r"(dst), "l"(src) : "memory");
}
__device__ __forceinline__ void cp_commit() {
    asm volatile("cp.async.commit_group;" ::: "memory");
}
template <int N>
__device__ __forceinline__ void cp_wait() {
    asm volatile("cp.async.wait_group %0;" :: "n"(N) : "memory");
}

__device__ __forceinline__ void ldsm4(uint32_t& r0, uint32_t& r1,
                                      uint32_t& r2, uint32_t& r3, uint32_t a) {
    asm volatile("ldmatrix.sync.aligned.m8n8.x4.shared.b16 {%0,%1,%2,%3}, [%4];"
                 : "=r"(r0), "=r"(r1), "=r"(r2), "=r"(r3) : "r"(a));
}
// B stored [n][k] (k contiguous) == col-major k x n: NON-transposed ldmatrix
// yields b0 = B[n=t/4][k=2(t%4)+j] which is exactly the m16n8k16 B fragment.
__device__ __forceinline__ void ldsm2(uint32_t& r0, uint32_t& r1, uint32_t a) {
    asm volatile("ldmatrix.sync.aligned.m8n8.x2.shared.b16 {%0,%1}, [%2];"
                 : "=r"(r0), "=r"(r1) : "r"(a));
}
__device__ __forceinline__ void mma16816(float* c, const uint32_t* a,
                                         const uint32_t* b) {
    asm volatile(
        "mma.sync.aligned.m16n8k16.row.col.f32.bf16.bf16.f32 "
        "{%0,%1,%2,%3}, {%4,%5,%6,%7}, {%8,%9}, {%0,%1,%2,%3};"
        : "+f"(c[0]), "+f"(c[1]), "+f"(c[2]), "+f"(c[3])
        : "r"(a[0]), "r"(a[1]), "r"(a[2]), "r"(a[3]), "r"(b[0]), "r"(b[1]));
}

// ---------------------------------------------------------------------------
// RoPE tables
// ---------------------------------------------------------------------------
__global__ void build_rope_tables()
{
    int idx = blockIdx.x * blockDim.x + threadIdx.x;
    int t = idx >> 6;
    int j = idx & 63;
    float invf = (float)pow(10000.0, -(double)j / 64.0);
    float ang = (float)t * invf;
    g_cos[idx] = (float)cos((double)ang);
    g_sin[idx] = (float)sin((double)ang);
}

// ---------------------------------------------------------------------------
// fp32 -> (bf16 hi, bf16 lo) split
// ---------------------------------------------------------------------------
__global__ void split_bf16(const float4* __restrict__ src,
                           __nv_bfloat162* __restrict__ hi,
                           __nv_bfloat162* __restrict__ lo)
{
    int i = blockIdx.x * blockDim.x + threadIdx.x;
    float4 v = src[i];
    __nv_bfloat162 h0 = __floats2bfloat162_rn(v.x, v.y);
    __nv_bfloat162 h1 = __floats2bfloat162_rn(v.z, v.w);
    __nv_bfloat162 l0 = __floats2bfloat162_rn(v.x - __bfloat162float(h0.x),
                                              v.y - __bfloat162float(h0.y));
    __nv_bfloat162 l1 = __floats2bfloat162_rn(v.z - __bfloat162float(h1.x),
                                              v.w - __bfloat162float(h1.y));
    hi[2 * i] = h0; hi[2 * i + 1] = h1;
    lo[2 * i] = l0; lo[2 * i + 1] = l1;
}

// ---------------------------------------------------------------------------
// mma.sync GEMM: C[M,N] = A[M,K]*B[N,K]^T, 3-term bf16 split.
// CTA 128x128, BK=64, 256 threads (8 warps, warp tile 64x32),
// cp.async double buffer, SW128-swizzled smem (128B rows).
// MODE 1 fuses C = (1-lamb)*C + lamb*vi.
// ---------------------------------------------------------------------------
#define OPND 16384                       // one operand tile: 128x64 bf16
#define STAGE (4 * OPND)                 // Ah, Al, Bh, Bl
#define GM_SMEM (2 * STAGE)              // 131072 B

template <int MODE>
__global__ __launch_bounds__(256, 1)
void gemm_mma(const __nv_bfloat16* __restrict__ Ahi, const __nv_bfloat16* __restrict__ Alo,
              const __nv_bfloat16* __restrict__ Bhi, const __nv_bfloat16* __restrict__ Blo,
              float* __restrict__ C,
              const float* __restrict__ vi, const float* __restrict__ lambp)
{
    extern __shared__ char smc[];
    const uint32_t sb = smem_u32(smc);
    const int tid = threadIdx.x;
    const int wid = tid >> 5;
    const int lid = tid & 31;
    const int warp_m = wid & 1;          // 0..1 -> 64-row slab
    const int warp_n = wid >> 1;         // 0..3 -> 32-col slab
    const int m0 = blockIdx.y * 128;
    const int n0 = blockIdx.x * 128;

    const __nv_bfloat16* srcs[4] = { Ahi + (size_t)m0 * DIM, Alo + (size_t)m0 * DIM,
                                     Bhi + (size_t)n0 * DIM, Blo + (size_t)n0 * DIM };

    // cp.async indexing: thread covers 4 16B-units per operand
    const int ldrow = tid >> 3;          // 0..31 (row base; +32 per q)
    const int ldu   = tid & 7;           // 16B unit 0..7 within 128B row

    auto load_chunk = [&](int chunk, int stage) {
        const int k0 = chunk * 64;
        #pragma unroll
        for (int t = 0; t < 4; t++) {
            const __nv_bfloat16* s = srcs[t] + k0 + ldu * 8;
            uint32_t dbase = sb + stage * STAGE + t * OPND;
            #pragma unroll
            for (int q = 0; q < 4; q++) {
                int row = ldrow + q * 32;
                cp16(dbase + SW128((uint32_t)(row * 128 + ldu * 16)),
                     s + (size_t)row * DIM);
            }
        }
        cp_commit();
    };

    float acc[4][4][4];
    #pragma unroll
    for (int a = 0; a < 4; a++)
        #pragma unroll
        for (int b = 0; b < 4; b++)
            #pragma unroll
            for (int c = 0; c < 4; c++) acc[a][b][c] = 0.f;

    // precomputed ldmatrix lane offsets (row part only; k-unit added per step)
    const int aq = lid >> 3;                                   // 0..3
    const int a_row = warp_m * 64 + (aq & 1) * 8 + (lid & 7);  // + mt*16
    const int a_ku  = aq >> 1;                                 // 0/1 extra 16B
    const int b_row = warp_n * 32 + (lid & 7);                 // + nt*8
    const int b_ku  = (lid >> 3) & 1;

    load_chunk(0, 0);

    for (int i = 0; i < 32; i++) {
        if (i + 1 < 32) { load_chunk(i + 1, (i + 1) & 1); cp_wait<1>(); }
        else            { cp_wait<0>(); }
        __syncthreads();

        const uint32_t st = sb + (i & 1) * STAGE;
        const uint32_t bAh = st, bAl = st + OPND, bBh = st + 2 * OPND, bBl = st + 3 * OPND;

        #pragma unroll
        for (int ks = 0; ks < 4; ks++) {
            uint32_t bh[8], bl[8];
            #pragma unroll
            for (int nt = 0; nt < 4; nt++) {
                uint32_t off = SW128((uint32_t)((b_row + nt * 8) * 128 + (ks * 2 + b_ku) * 16));
                ldsm2(bh[nt * 2], bh[nt * 2 + 1], bBh + off);
                ldsm2(bl[nt * 2], bl[nt * 2 + 1], bBl + off);
            }
            #pragma unroll
            for (int mt = 0; mt < 4; mt++) {
                uint32_t off = SW128((uint32_t)((a_row + mt * 16) * 128 + (ks * 2 + a_ku) * 16));
                uint32_t ah[4], al[4];
                ldsm4(ah[0], ah[1], ah[2], ah[3], bAh + off);
                ldsm4(al[0], al[1], al[2], al[3], bAl + off);
                #pragma unroll
                for (int nt = 0; nt < 4; nt++) {
                    mma16816(acc[mt][nt], ah, &bh[nt * 2]);
                    mma16816(acc[mt][nt], ah, &bl[nt * 2]);
                    mma16816(acc[mt][nt], al, &bh[nt * 2]);
                }
            }
        }
        __syncthreads();
    }

    // epilogue
    float lam = 0.f, oml = 1.f;
    if (MODE == 1) { lam = *lambp; oml = 1.f - lam; }
    const int gid = lid >> 2;            // groupID 0..7
    const int tg  = lid & 3;
    #pragma unroll
    for (int mt = 0; mt < 4; mt++) {
        #pragma unroll
        for (int nt = 0; nt < 4; nt++) {
            int r = m0 + warp_m * 64 + mt * 16 + gid;
            int c = n0 + warp_n * 32 + nt * 8 + tg * 2;
            float2 v01 = make_float2(acc[mt][nt][0], acc[mt][nt][1]);
            float2 v23 = make_float2(acc[mt][nt][2], acc[mt][nt][3]);
            if (MODE == 1) {
                float2 w0 = *(const float2*)(vi + (size_t)r * DIM + c);
                float2 w1 = *(const float2*)(vi + (size_t)(r + 8) * DIM + c);
                v01.x = oml * v01.x + lam * w0.x; v01.y = oml * v01.y + lam * w0.y;
                v23.x = oml * v23.x + lam * w1.x; v23.y = oml * v23.y + lam * w1.y;
            }
            *(float2*)(C + (size_t)r * DIM + c) = v01;
            *(float2*)(C + (size_t)(r + 8) * DIM + c) = v23;
        }
    }
}

// ---------------------------------------------------------------------------
// Fused RMSNorm + RoPE
// ---------------------------------------------------------------------------
__global__ void rmsnorm_rope(float* __restrict__ Q, float* __restrict__ K)
{
    const int t = blockIdx.x;
    const int h = blockIdx.y;
    float* row = (blockIdx.z == 0 ? Q : K) + t * 2048 + h * 128;
    const int i = threadIdx.x;

    float v = row[i];
    float ss = v * v;
    #pragma unroll
    for (int o = 16; o > 0; o >>= 1) ss += __shfl_xor_sync(0xffffffffu, ss, o);

    __shared__ float red[4];
    __shared__ float vals[128];
    if ((i & 31) == 0) red[i >> 5] = ss;
    __syncthreads();
    float tot = red[0] + red[1] + red[2] + red[3];
    float nv = v * rsqrtf(tot * (1.f / 128.f) + EPSF);
    vals[i] = nv;
    __syncthreads();

    if (i < 64) {
        float x1 = vals[i], x2 = vals[i + 64];
        float c = g_cos[t * 64 + i];
        float s = g_sin[t * 64 + i];
        row[i]      = x1 * c + x2 * s;
        row[i + 64] = x2 * c - x1 * s;
    }
}

// ---------------------------------------------------------------------------
// Causal flash attention (fp32 SIMT), epilogue writes bf16 hi/lo of Y.
// ---------------------------------------------------------------------------
#define FL_SMEM_FLOATS (2 * 128 * 68 + 64 * 132 + 64 * 68)
#define FL_SMEM_BYTES  (FL_SMEM_FLOATS * 4)

__global__ __launch_bounds__(256, 1)
void flash_attn()
{
    extern __shared__ float sm[];
    float* Qt = sm;                               // [128][68]
    float* Kt = sm + 128 * 68;                    // [128][68]
    float* Vs = sm + 2 * 128 * 68;                // [64][132]
    float* Pt = sm + 2 * 128 * 68 + 64 * 132;     // [64][68]

    const int qb  = blockIdx.x;
    const int h   = blockIdx.y;
    const int tid = threadIdx.x;
    const int ty  = tid >> 4;
    const int tx  = tid & 15;
    const int q0  = qb * 64;

    for (int idx = tid; idx < 64 * 128; idx += 256) {
        int r = idx >> 7, d = idx & 127;
        Qt[d * 68 + r] = g_Q[(q0 + r) * 2048 + h * 128 + d];
    }
    __syncthreads();

    float m[4], l[4], o[4][8];
    #pragma unroll
    for (int i = 0; i < 4; i++) {
        m[i] = -1e30f; l[i] = 0.f;
        #pragma unroll
        for (int j = 0; j < 8; j++) o[i][j] = 0.f;
    }

    for (int kb = 0; kb <= qb; kb++) {
        const int k0 = kb * 64;
        for (int idx = tid; idx < 64 * 128; idx += 256) {
            int c = idx >> 7, d = idx & 127;
            Kt[d * 68 + c]  = g_K[(k0 + c) * 2048 + h * 128 + d];
            Vs[c * 132 + d] = g_V[(k0 + c) * 2048 + h * 128 + d];
        }
        __syncthreads();

        float s[4][4];
        #pragma unroll
        for (int i = 0; i < 4; i++)
            #pragma unroll
            for (int j = 0; j < 4; j++) s[i][j] = 0.f;

        #pragma unroll 8
        for (int d = 0; d < 128; d++) {
            float4 qf = *(const float4*)&Qt[d * 68 + ty * 4];
            float4 kf = *(const float4*)&Kt[d * 68 + tx * 4];
            float qa[4] = {qf.x, qf.y, qf.z, qf.w};
            float ka[4] = {kf.x, kf.y, kf.z, kf.w};
            #pragma unroll
            for (int i = 0; i < 4; i++)
                #pragma unroll
                for (int j = 0; j < 4; j++)
                    s[i][j] = fmaf(qa[i], ka[j], s[i][j]);
        }

        const bool diag = (kb == qb);
        #pragma unroll
        for (int i = 0; i < 4; i++)
            #pragma unroll
            for (int j = 0; j < 4; j++) {
                s[i][j] *= ATT_SCALE;
                if (diag && (k0 + tx * 4 + j > q0 + ty * 4 + i)) s[i][j] = -1e30f;
            }

        float mb[4];
        #pragma unroll
        for (int i = 0; i < 4; i++) {
            mb[i] = fmaxf(fmaxf(s[i][0], s[i][1]), fmaxf(s[i][2], s[i][3]));
            #pragma unroll
            for (int off = 8; off > 0; off >>= 1)
                mb[i] = fmaxf(mb[i], __shfl_xor_sync(0xffffffffu, mb[i], off));
        }
        float al[4];
        #pragma unroll
        for (int i = 0; i < 4; i++) {
            float mn = fmaxf(m[i], mb[i]);
            al[i] = __expf(m[i] - mn);
            m[i] = mn;
        }
        float p[4][4], rs[4];
        #pragma unroll
        for (int i = 0; i < 4; i++) {
            #pragma unroll
            for (int j = 0; j < 4; j++) p[i][j] = __expf(s[i][j] - m[i]);
            rs[i] = p[i][0] + p[i][1] + p[i][2] + p[i][3];
            #pragma unroll
            for (int off = 8; off > 0; off >>= 1)
                rs[i] += __shfl_xor_sync(0xffffffffu, rs[i], off);
            l[i] = l[i] * al[i] + rs[i];
            #pragma unroll
            for (int j = 0; j < 8; j++) o[i][j] *= al[i];
        }

        #pragma unroll
        for (int j = 0; j < 4; j++) {
            float4 pv = make_float4(p[0][j], p[1][j], p[2][j], p[3][j]);
            *(float4*)&Pt[(tx * 4 + j) * 68 + ty * 4] = pv;
        }
        __syncthreads();

        #pragma unroll 4
        for (int c = 0; c < 64; c++) {
            float4 pf = *(const float4*)&Pt[c * 68 + ty * 4];
            float4 v0 = *(const float4*)&Vs[c * 132 + tx * 8];
            float4 v1 = *(const float4*)&Vs[c * 132 + tx * 8 + 4];
            float pa[4] = {pf.x, pf.y, pf.z, pf.w};
            float va[8] = {v0.x, v0.y, v0.z, v0.w, v1.x, v1.y, v1.z, v1.w};
            #pragma unroll
            for (int i = 0; i < 4; i++)
                #pragma unroll
                for (int j = 0; j < 8; j++)
                    o[i][j] = fmaf(pa[i], va[j], o[i][j]);
        }
        __syncthreads();
    }

    // epilogue: write Y as bf16 hi/lo (feeds proj GEMM)
    #pragma unroll
    for (int i = 0; i < 4; i++) {
        float inv = 1.f / l[i];
        int row = q0 + ty * 4 + i;
        int base = row * 2048 + h * 128 + tx * 8;
        __nv_bfloat162* yh = (__nv_bfloat162*)(g_Yhi + base);
        __nv_bfloat162* yl = (__nv_bfloat162*)(g_Ylo + base);
        #pragma unroll
        for (int jj = 0; jj < 4; jj++) {
            float a = o[i][2 * jj] * inv;
            float b = o[i][2 * jj + 1] * inv;
            __nv_bfloat162 hh = __floats2bfloat162_rn(a, b);
            __nv_bfloat162 ll = __floats2bfloat162_rn(a - __bfloat162float(hh.x),
                                                      b - __bfloat162float(hh.y));
            yh[jj] = hh;
            yl[jj] = ll;
        }
    }
}

// ---------------------------------------------------------------------------
// Launch
// ---------------------------------------------------------------------------
extern "C" void kernel_launch(void* const* d_in, const int* in_sizes, int n_in,
                              void* d_out, int out_size)
{
    (void)in_sizes; (void)n_in; (void)out_size;
    const float* x    = (const float*)d_in[0];
    const float* vi   = (const float*)d_in[1];
    const float* Wq   = (const float*)d_in[2];
    const float* Wk   = (const float*)d_in[3];
    const float* Wv   = (const float*)d_in[4];
    const float* Wp   = (const float*)d_in[5];
    const float* lamb = (const float*)d_in[6];
    float* out = (float*)d_out;

    float *Qp, *Kp, *Vp;
    __nv_bfloat16 *Xhi, *Xlo, *Yhi, *Ylo, *Whi, *Wlo;
    cudaGetSymbolAddress((void**)&Qp, g_Q);
    cudaGetSymbolAddress((void**)&Kp, g_K);
    cudaGetSymbolAddress((void**)&Vp, g_V);
    cudaGetSymbolAddress((void**)&Xhi, g_Xhi);
    cudaGetSymbolAddress((void**)&Xlo, g_Xlo);
    cudaGetSymbolAddress((void**)&Yhi, g_Yhi);
    cudaGetSymbolAddress((void**)&Ylo, g_Ylo);
    cudaGetSymbolAddress((void**)&Whi, g_Whi);
    cudaGetSymbolAddress((void**)&Wlo, g_Wlo);

    build_rope_tables<<<(SEQ * 64) / 256, 256>>>();

    split_bf16<<<(SEQ * DIM / 4) / 256, 256>>>((const float4*)x,
        (__nv_bfloat162*)Xhi, (__nv_bfloat162*)Xlo);
    const float* Ws[4] = {Wq, Wk, Wv, Wp};
    for (int w = 0; w < 4; w++) {
        split_bf16<<<(DIM * DIM / 4) / 256, 256>>>((const float4*)Ws[w],
            (__nv_bfloat162*)(Whi + (size_t)w * DIM * DIM),
            (__nv_bfloat162*)(Wlo + (size_t)w * DIM * DIM));
    }

    cudaFuncSetAttribute(gemm_mma<0>, cudaFuncAttributeMaxDynamicSharedMemorySize, GM_SMEM);
    cudaFuncSetAttribute(gemm_mma<1>, cudaFuncAttributeMaxDynamicSharedMemorySize, GM_SMEM);

    dim3 gg(DIM / 128, SEQ / 128);
    gemm_mma<0><<<gg, 256, GM_SMEM>>>(Xhi, Xlo,
        Whi + 0 * (size_t)DIM * DIM, Wlo + 0 * (size_t)DIM * DIM, Qp, nullptr, nullptr);
    gemm_mma<0><<<gg, 256, GM_SMEM>>>(Xhi, Xlo,
        Whi + 1 * (size_t)DIM * DIM, Wlo + 1 * (size_t)DIM * DIM, Kp, nullptr, nullptr);
    gemm_mma<1><<<gg, 256, GM_SMEM>>>(Xhi, Xlo,
        Whi + 2 * (size_t)DIM * DIM, Wlo + 2 * (size_t)DIM * DIM, Vp, vi, lamb);

    rmsnorm_rope<<<dim3(SEQ, NHEAD, 2), 128>>>(Qp, Kp);

    cudaFuncSetAttribute(flash_attn,
                         cudaFuncAttributeMaxDynamicSharedMemorySize, FL_SMEM_BYTES);
    flash_attn<<<dim3(SEQ / 64, NHEAD), 256, FL_SMEM_BYTES>>>();

    gemm_mma<0><<<gg, 256, GM_SMEM>>>(Yhi, Ylo,
        Whi + 3 * (size_t)DIM * DIM, Wlo + 3 * (size_t)DIM * DIM, out, nullptr, nullptr);
}

// round 7
// speedup vs baseline: 3.3901x; 2.1583x over previous
#include <cuda_runtime.h>
#include <cuda_bf16.h>
#include <math.h>
#include <stdint.h>

#define SEQ   4096
#define DIM   2048
#define NHEAD 16
#define HDIM  128
#define EPSF  1.1920929e-07f
#define ATT_SCALE 0.08838834764831845f  // 128^-0.5

#define SW128(o) ((o) ^ (((o) >> 3) & 0x70))

// ---------------------------------------------------------------------------
// Scratch (device globals; no allocation allowed)
// ---------------------------------------------------------------------------
__device__ float g_Q[SEQ * DIM];
__device__ float g_K[SEQ * DIM];
__device__ float g_V[SEQ * DIM];
__device__ float g_cos[SEQ * (HDIM / 2)];
__device__ float g_sin[SEQ * (HDIM / 2)];
__device__ __nv_bfloat16 g_Xhi[SEQ * DIM];
__device__ __nv_bfloat16 g_Xlo[SEQ * DIM];
__device__ __nv_bfloat16 g_Yhi[SEQ * DIM];
__device__ __nv_bfloat16 g_Ylo[SEQ * DIM];
__device__ __nv_bfloat16 g_Whi[4 * DIM * DIM];
__device__ __nv_bfloat16 g_Wlo[4 * DIM * DIM];
// flash inputs (bf16 hi/lo)
__device__ __nv_bfloat16 g_Qh[SEQ * DIM];
__device__ __nv_bfloat16 g_Ql[SEQ * DIM];
__device__ __nv_bfloat16 g_Kh[SEQ * DIM];
__device__ __nv_bfloat16 g_Kl[SEQ * DIM];
__device__ __nv_bfloat16 g_Vth[DIM * SEQ];   // transposed: [dim][t]
__device__ __nv_bfloat16 g_Vtl[DIM * SEQ];

// ---------------------------------------------------------------------------
// PTX helpers (baseline sm_80+ only — harness target is plain sm_100)
// ---------------------------------------------------------------------------
__device__ __forceinline__ uint32_t smem_u32(const void* p) {
    uint32_t a;
    asm("{ .reg .u64 t; cvta.to.shared.u64 t, %1; cvt.u32.u64 %0, t; }"
        : "=r"(a) : "l"(p));
    return a;
}
__device__ __forceinline__ void cp16(uint32_t dst, const void* src) {
    asm volatile("cp.async.cg.shared.global [%0], [%1], 16;"
                 :: "r"(dst), "l"(src) : "memory");
}
__device__ __forceinline__ void cp_commit() {
    asm volatile("cp.async.commit_group;" ::: "memory");
}
template <int N>
__device__ __forceinline__ void cp_wait() {
    asm volatile("cp.async.wait_group %0;" :: "n"(N) : "memory");
}
__device__ __forceinline__ void ldsm4(uint32_t& r0, uint32_t& r1,
                                      uint32_t& r2, uint32_t& r3, uint32_t a) {
    asm volatile("ldmatrix.sync.aligned.m8n8.x4.shared.b16 {%0,%1,%2,%3}, [%4];"
                 : "=r"(r0), "=r"(r1), "=r"(r2), "=r"(r3) : "r"(a));
}
__device__ __forceinline__ void ldsm2(uint32_t& r0, uint32_t& r1, uint32_t a) {
    asm volatile("ldmatrix.sync.aligned.m8n8.x2.shared.b16 {%0,%1}, [%2];"
                 : "=r"(r0), "=r"(r1) : "r"(a));
}
__device__ __forceinline__ void mma16816(float* c, const uint32_t* a,
                                         const uint32_t* b) {
    asm volatile(
        "mma.sync.aligned.m16n8k16.row.col.f32.bf16.bf16.f32 "
        "{%0,%1,%2,%3}, {%4,%5,%6,%7}, {%8,%9}, {%0,%1,%2,%3};"
        : "+f"(c[0]), "+f"(c[1]), "+f"(c[2]), "+f"(c[3])
        : "r"(a[0]), "r"(a[1]), "r"(a[2]), "r"(a[3]), "r"(b[0]), "r"(b[1]));
}
// fast exp for x <= 0, rel err ~2.4e-6, FMA-pipe only (no MUFU)
__device__ __forceinline__ float fexp(float x) {
    float z = fmaxf(x * 1.4426950408889634f, -120.f);
    float n = rintf(z);
    float f = z - n;                       // [-0.5, 0.5]
    float p = fmaf(0.0013333558f, f, 0.0096181291f);
    p = fmaf(p, f, 0.0555041087f);
    p = fmaf(p, f, 0.2402265070f);
    p = fmaf(p, f, 0.6931471806f);
    p = fmaf(p, f, 1.0f);
    return p * __int_as_float(((int)n + 127) << 23);
}
__device__ __forceinline__ uint32_t pack_split(float a, float b, uint32_t& lo) {
    __nv_bfloat162 h = __floats2bfloat162_rn(a, b);
    __nv_bfloat162 l = __floats2bfloat162_rn(a - __bfloat162float(h.x),
                                             b - __bfloat162float(h.y));
    lo = *reinterpret_cast<uint32_t*>(&l);
    return *reinterpret_cast<uint32_t*>(&h);
}

// ---------------------------------------------------------------------------
// RoPE tables
// ---------------------------------------------------------------------------
__global__ void build_rope_tables()
{
    int idx = blockIdx.x * blockDim.x + threadIdx.x;
    int t = idx >> 6;
    int j = idx & 63;
    float invf = (float)pow(10000.0, -(double)j / 64.0);
    float ang = (float)t * invf;
    g_cos[idx] = (float)cos((double)ang);
    g_sin[idx] = (float)sin((double)ang);
}

// ---------------------------------------------------------------------------
// fp32 -> (bf16 hi, bf16 lo) split
// ---------------------------------------------------------------------------
__global__ void split_bf16(const float4* __restrict__ src,
                           __nv_bfloat162* __restrict__ hi,
                           __nv_bfloat162* __restrict__ lo)
{
    int i = blockIdx.x * blockDim.x + threadIdx.x;
    float4 v = src[i];
    uint32_t l0, l1;
    uint32_t h0 = pack_split(v.x, v.y, l0);
    uint32_t h1 = pack_split(v.z, v.w, l1);
    ((uint32_t*)hi)[2 * i] = h0; ((uint32_t*)hi)[2 * i + 1] = h1;
    ((uint32_t*)lo)[2 * i] = l0; ((uint32_t*)lo)[2 * i + 1] = l1;
}

// ---------------------------------------------------------------------------
// mma.sync GEMM (unchanged from R6): C = A*B^T, 3-term bf16 split.
// ---------------------------------------------------------------------------
#define OPND 16384
#define STAGE (4 * OPND)
#define GM_SMEM (2 * STAGE)

template <int MODE>
__global__ __launch_bounds__(256, 1)
void gemm_mma(const __nv_bfloat16* __restrict__ Ahi, const __nv_bfloat16* __restrict__ Alo,
              const __nv_bfloat16* __restrict__ Bhi, const __nv_bfloat16* __restrict__ Blo,
              float* __restrict__ C,
              const float* __restrict__ vi, const float* __restrict__ lambp)
{
    extern __shared__ char smc[];
    const uint32_t sb = smem_u32(smc);
    const int tid = threadIdx.x;
    const int wid = tid >> 5;
    const int lid = tid & 31;
    const int warp_m = wid & 1;
    const int warp_n = wid >> 1;
    const int m0 = blockIdx.y * 128;
    const int n0 = blockIdx.x * 128;

    const __nv_bfloat16* srcs[4] = { Ahi + (size_t)m0 * DIM, Alo + (size_t)m0 * DIM,
                                     Bhi + (size_t)n0 * DIM, Blo + (size_t)n0 * DIM };
    const int ldrow = tid >> 3;
    const int ldu   = tid & 7;

    auto load_chunk = [&](int chunk, int stage) {
        const int k0 = chunk * 64;
        #pragma unroll
        for (int t = 0; t < 4; t++) {
            const __nv_bfloat16* s = srcs[t] + k0 + ldu * 8;
            uint32_t dbase = sb + stage * STAGE + t * OPND;
            #pragma unroll
            for (int q = 0; q < 4; q++) {
                int row = ldrow + q * 32;
                cp16(dbase + SW128((uint32_t)(row * 128 + ldu * 16)),
                     s + (size_t)row * DIM);
            }
        }
        cp_commit();
    };

    float acc[4][4][4];
    #pragma unroll
    for (int a = 0; a < 4; a++)
        #pragma unroll
        for (int b = 0; b < 4; b++)
            #pragma unroll
            for (int c = 0; c < 4; c++) acc[a][b][c] = 0.f;

    const int aq = lid >> 3;
    const int a_row = warp_m * 64 + (aq & 1) * 8 + (lid & 7);
    const int a_ku  = aq >> 1;
    const int b_row = warp_n * 32 + (lid & 7);
    const int b_ku  = (lid >> 3) & 1;

    load_chunk(0, 0);

    for (int i = 0; i < 32; i++) {
        if (i + 1 < 32) { load_chunk(i + 1, (i + 1) & 1); cp_wait<1>(); }
        else            { cp_wait<0>(); }
        __syncthreads();

        const uint32_t st = sb + (i & 1) * STAGE;
        const uint32_t bAh = st, bAl = st + OPND, bBh = st + 2 * OPND, bBl = st + 3 * OPND;

        #pragma unroll
        for (int ks = 0; ks < 4; ks++) {
            uint32_t bh[8], bl[8];
            #pragma unroll
            for (int nt = 0; nt < 4; nt++) {
                uint32_t off = SW128((uint32_t)((b_row + nt * 8) * 128 + (ks * 2 + b_ku) * 16));
                ldsm2(bh[nt * 2], bh[nt * 2 + 1], bBh + off);
                ldsm2(bl[nt * 2], bl[nt * 2 + 1], bBl + off);
            }
            #pragma unroll
            for (int mt = 0; mt < 4; mt++) {
                uint32_t off = SW128((uint32_t)((a_row + mt * 16) * 128 + (ks * 2 + a_ku) * 16));
                uint32_t ah[4], al[4];
                ldsm4(ah[0], ah[1], ah[2], ah[3], bAh + off);
                ldsm4(al[0], al[1], al[2], al[3], bAl + off);
                #pragma unroll
                for (int nt = 0; nt < 4; nt++) {
                    mma16816(acc[mt][nt], ah, &bh[nt * 2]);
                    mma16816(acc[mt][nt], ah, &bl[nt * 2]);
                    mma16816(acc[mt][nt], al, &bh[nt * 2]);
                }
            }
        }
        __syncthreads();
    }

    float lam = 0.f, oml = 1.f;
    if (MODE == 1) { lam = *lambp; oml = 1.f - lam; }
    const int gid = lid >> 2;
    const int tg  = lid & 3;
    #pragma unroll
    for (int mt = 0; mt < 4; mt++) {
        #pragma unroll
        for (int nt = 0; nt < 4; nt++) {
            int r = m0 + warp_m * 64 + mt * 16 + gid;
            int c = n0 + warp_n * 32 + nt * 8 + tg * 2;
            float2 v01 = make_float2(acc[mt][nt][0], acc[mt][nt][1]);
            float2 v23 = make_float2(acc[mt][nt][2], acc[mt][nt][3]);
            if (MODE == 1) {
                float2 w0 = *(const float2*)(vi + (size_t)r * DIM + c);
                float2 w1 = *(const float2*)(vi + (size_t)(r + 8) * DIM + c);
                v01.x = oml * v01.x + lam * w0.x; v01.y = oml * v01.y + lam * w0.y;
                v23.x = oml * v23.x + lam * w1.x; v23.y = oml * v23.y + lam * w1.y;
            }
            *(float2*)(C + (size_t)r * DIM + c) = v01;
            *(float2*)(C + (size_t)(r + 8) * DIM + c) = v23;
        }
    }
}

// ---------------------------------------------------------------------------
// Fused RMSNorm + RoPE, fp32 in -> bf16 hi/lo out
// ---------------------------------------------------------------------------
__global__ void rmsnorm_rope_split()
{
    const int t = blockIdx.x;
    const int h = blockIdx.y;
    const int z = blockIdx.z;
    const float* row = (z == 0 ? g_Q : g_K) + t * 2048 + h * 128;
    __nv_bfloat16* oh = (z == 0 ? g_Qh : g_Kh) + t * 2048 + h * 128;
    __nv_bfloat16* ol = (z == 0 ? g_Ql : g_Kl) + t * 2048 + h * 128;
    const int i = threadIdx.x;

    float v = row[i];
    float ss = v * v;
    #pragma unroll
    for (int o = 16; o > 0; o >>= 1) ss += __shfl_xor_sync(0xffffffffu, ss, o);

    __shared__ float red[4];
    __shared__ float vals[128];
    if ((i & 31) == 0) red[i >> 5] = ss;
    __syncthreads();
    float tot = red[0] + red[1] + red[2] + red[3];
    vals[i] = v * rsqrtf(tot * (1.f / 128.f) + EPSF);
    __syncthreads();

    float out;
    if (i < 64) {
        out = vals[i] * g_cos[t * 64 + i] + vals[i + 64] * g_sin[t * 64 + i];
    } else {
        int j = i - 64;
        out = vals[i] * g_cos[t * 64 + j] - vals[i - 64] * g_sin[t * 64 + j];
    }
    __nv_bfloat16 hh = __float2bfloat16_rn(out);
    oh[i] = hh;
    ol[i] = __float2bfloat16_rn(out - __bfloat162float(hh));
}

// ---------------------------------------------------------------------------
// V fp32 [t][dim] -> transposed bf16 hi/lo [dim][t]
// ---------------------------------------------------------------------------
__global__ void transpose_split_v()
{
    __shared__ float tile[32][33];
    const int t0 = blockIdx.x * 32;
    const int d0 = blockIdx.y * 32;
    const int tx = threadIdx.x, ty = threadIdx.y;
    #pragma unroll
    for (int r = ty; r < 32; r += 8)
        tile[r][tx] = g_V[(size_t)(t0 + r) * DIM + d0 + tx];
    __syncthreads();
    #pragma unroll
    for (int r = ty; r < 32; r += 8) {
        float v = tile[tx][r];
        __nv_bfloat16 hh = __float2bfloat16_rn(v);
        size_t o = (size_t)(d0 + r) * SEQ + t0 + tx;
        g_Vth[o] = hh;
        g_Vtl[o] = __float2bfloat16_rn(v - __bfloat162float(hh));
    }
}

// ---------------------------------------------------------------------------
// Tensor-core causal flash attention.
// BM=128 q-rows x BN=64 keys, 8 warps (16 rows each), 3-term bf16 split for
// both S = Q K^T and O += P V. P stays in registers (C-frag == A-frag).
// smem: Qh/Ql [128][136] pad, Kh/Kl 2-stage [64][136], Vh/Vl 2-stage [128][72].
// ---------------------------------------------------------------------------
#define FA_SMEM 212992

__global__ __launch_bounds__(256, 1)
void flash_mma()
{
    extern __shared__ char fsm[];
    const uint32_t sb = smem_u32(fsm);
    const int tid = threadIdx.x;
    const int wid = tid >> 5;
    const int lid = tid & 31;
    const int qb  = (int)gridDim.x - 1 - (int)blockIdx.x;  // longest first
    const int h   = blockIdx.y;
    const int q0  = qb * 128;
    const int nkb = 2 * qb + 2;

    const uint32_t oQH = 0,      oQL = 34816;
    const uint32_t oKH = 69632,  oKL = 104448;   // + stage*17408
    const uint32_t oVH = 139264, oVL = 176128;   // + stage*18432

    const __nv_bfloat16* Qhg = g_Qh + (size_t)q0 * DIM + h * 128;
    const __nv_bfloat16* Qlg = g_Ql + (size_t)q0 * DIM + h * 128;

    // Q load (own commit group)
    #pragma unroll
    for (int q = 0; q < 8; q++) {
        int u = tid + q * 256;
        int row = u >> 4, cu = u & 15;
        cp16(sb + oQH + row * 272 + cu * 16, Qhg + (size_t)row * DIM + cu * 8);
        cp16(sb + oQL + row * 272 + cu * 16, Qlg + (size_t)row * DIM + cu * 8);
    }
    cp_commit();

    auto load_kv = [&](int kb, int st) {
        const int k0 = kb * 64;
        const __nv_bfloat16* kh = g_Kh + (size_t)k0 * DIM + h * 128;
        const __nv_bfloat16* kl = g_Kl + (size_t)k0 * DIM + h * 128;
        const uint32_t kdh = sb + oKH + st * 17408;
        const uint32_t kdl = sb + oKL + st * 17408;
        #pragma unroll
        for (int q = 0; q < 4; q++) {
            int u = tid + q * 256;
            int row = u >> 4, cu = u & 15;
            cp16(kdh + row * 272 + cu * 16, kh + (size_t)row * DIM + cu * 8);
            cp16(kdl + row * 272 + cu * 16, kl + (size_t)row * DIM + cu * 8);
        }
        const __nv_bfloat16* vh = g_Vth + (size_t)(h * 128) * SEQ + k0;
        const __nv_bfloat16* vl = g_Vtl + (size_t)(h * 128) * SEQ + k0;
        const uint32_t vdh = sb + oVH + st * 18432;
        const uint32_t vdl = sb + oVL + st * 18432;
        #pragma unroll
        for (int q = 0; q < 4; q++) {
            int u = tid + q * 256;
            int row = u >> 3, cu = u & 7;
            cp16(vdh + row * 144 + cu * 16, vh + (size_t)row * SEQ + cu * 8);
            cp16(vdl + row * 144 + cu * 16, vl + (size_t)row * SEQ + cu * 8);
        }
        cp_commit();
    };

    load_kv(0, 0);

    float m0r = -1e30f, m1r = -1e30f, l0 = 0.f, l1 = 0.f;
    float o[16][4];
    #pragma unroll
    for (int d = 0; d < 16; d++)
        #pragma unroll
        for (int j = 0; j < 4; j++) o[d][j] = 0.f;

    // fragment address components
    const int aq   = lid >> 3;
    const int arow = wid * 16 + (aq & 1) * 8 + (lid & 7);
    const int aku  = aq >> 1;
    const int brow = ((lid >> 4) << 3) + (lid & 7);  // nt_off*8 + lane row
    const int bku  = (lid >> 3) & 1;

    for (int kb = 0; kb < nkb; kb++) {
        if (kb + 1 < nkb) { load_kv(kb + 1, (kb + 1) & 1); cp_wait<1>(); }
        else              { cp_wait<0>(); }
        __syncthreads();

        const uint32_t kbh = sb + oKH + (kb & 1) * 17408;
        const uint32_t kbl = sb + oKL + (kb & 1) * 17408;
        const uint32_t vbh = sb + oVH + (kb & 1) * 18432;
        const uint32_t vbl = sb + oVL + (kb & 1) * 18432;

        // ---- S = Q K^T (16x64 per warp) ----
        float s[8][4];
        #pragma unroll
        for (int nt = 0; nt < 8; nt++)
            #pragma unroll
            for (int j = 0; j < 4; j++) s[nt][j] = 0.f;

        #pragma unroll
        for (int kt = 0; kt < 8; kt++) {
            uint32_t qh[4], ql[4];
            uint32_t qoff = (uint32_t)(arow * 272 + (kt * 2 + aku) * 16);
            ldsm4(qh[0], qh[1], qh[2], qh[3], sb + oQH + qoff);
            ldsm4(ql[0], ql[1], ql[2], ql[3], sb + oQL + qoff);
            #pragma unroll
            for (int np = 0; np < 4; np++) {
                uint32_t kh4[4], kl4[4];
                uint32_t koff = (uint32_t)((np * 16 + brow) * 272 + (kt * 2 + bku) * 16);
                ldsm4(kh4[0], kh4[1], kh4[2], kh4[3], kbh + koff);
                ldsm4(kl4[0], kl4[1], kl4[2], kl4[3], kbl + koff);
                mma16816(s[2 * np],     qh, &kh4[0]);
                mma16816(s[2 * np],     qh, &kl4[0]);
                mma16816(s[2 * np],     ql, &kh4[0]);
                mma16816(s[2 * np + 1], qh, &kh4[2]);
                mma16816(s[2 * np + 1], qh, &kl4[2]);
                mma16816(s[2 * np + 1], ql, &kh4[2]);
            }
        }

        // scale + causal mask
        #pragma unroll
        for (int nt = 0; nt < 8; nt++)
            #pragma unroll
            for (int j = 0; j < 4; j++) s[nt][j] *= ATT_SCALE;
        if (kb >= 2 * qb) {
            const int moff = (kb - 2 * qb) * 64;
            const int r0 = wid * 16 + (lid >> 2);
            #pragma unroll
            for (int nt = 0; nt < 8; nt++) {
                int c = nt * 8 + (lid & 3) * 2 + moff;
                if (c > r0)     s[nt][0] = -1e30f;
                if (c + 1 > r0) s[nt][1] = -1e30f;
                if (c > r0 + 8)     s[nt][2] = -1e30f;
                if (c + 1 > r0 + 8) s[nt][3] = -1e30f;
            }
        }

        // ---- online softmax (rows r0, r0+8 per thread; quad-lane reduce) ----
        float mx0 = -1e30f, mx1 = -1e30f;
        #pragma unroll
        for (int nt = 0; nt < 8; nt++) {
            mx0 = fmaxf(mx0, fmaxf(s[nt][0], s[nt][1]));
            mx1 = fmaxf(mx1, fmaxf(s[nt][2], s[nt][3]));
        }
        mx0 = fmaxf(mx0, __shfl_xor_sync(0xffffffffu, mx0, 1));
        mx0 = fmaxf(mx0, __shfl_xor_sync(0xffffffffu, mx0, 2));
        mx1 = fmaxf(mx1, __shfl_xor_sync(0xffffffffu, mx1, 1));
        mx1 = fmaxf(mx1, __shfl_xor_sync(0xffffffffu, mx1, 2));
        float nm0 = fmaxf(m0r, mx0), nm1 = fmaxf(m1r, mx1);
        float al0 = fexp(m0r - nm0), al1 = fexp(m1r - nm1);
        m0r = nm0; m1r = nm1;

        float rs0 = 0.f, rs1 = 0.f;
        #pragma unroll
        for (int nt = 0; nt < 8; nt++) {
            s[nt][0] = fexp(s[nt][0] - nm0);
            s[nt][1] = fexp(s[nt][1] - nm0);
            s[nt][2] = fexp(s[nt][2] - nm1);
            s[nt][3] = fexp(s[nt][3] - nm1);
            rs0 += s[nt][0] + s[nt][1];
            rs1 += s[nt][2] + s[nt][3];
        }
        rs0 += __shfl_xor_sync(0xffffffffu, rs0, 1);
        rs0 += __shfl_xor_sync(0xffffffffu, rs0, 2);
        rs1 += __shfl_xor_sync(0xffffffffu, rs1, 1);
        rs1 += __shfl_xor_sync(0xffffffffu, rs1, 2);
        l0 = l0 * al0 + rs0;
        l1 = l1 * al1 + rs1;
        #pragma unroll
        for (int d = 0; d < 16; d++) {
            o[d][0] *= al0; o[d][1] *= al0;
            o[d][2] *= al1; o[d][3] *= al1;
        }

        // ---- O += P V (P in registers as A-frags, hi/lo split) ----
        #pragma unroll
        for (int kt2 = 0; kt2 < 4; kt2++) {
            const int n0t = 2 * kt2, n1t = 2 * kt2 + 1;
            uint32_t ph[4], pl[4];
            ph[0] = pack_split(s[n0t][0], s[n0t][1], pl[0]);
            ph[1] = pack_split(s[n0t][2], s[n0t][3], pl[1]);
            ph[2] = pack_split(s[n1t][0], s[n1t][1], pl[2]);
            ph[3] = pack_split(s[n1t][2], s[n1t][3], pl[3]);
            #pragma unroll
            for (int dp = 0; dp < 8; dp++) {
                uint32_t vh4[4], vl4[4];
                uint32_t voff = (uint32_t)((dp * 16 + brow) * 144 + (kt2 * 2 + bku) * 16);
                ldsm4(vh4[0], vh4[1], vh4[2], vh4[3], vbh + voff);
                ldsm4(vl4[0], vl4[1], vl4[2], vl4[3], vbl + voff);
                mma16816(o[2 * dp],     ph, &vh4[0]);
                mma16816(o[2 * dp],     ph, &vl4[0]);
                mma16816(o[2 * dp],     pl, &vh4[0]);
                mma16816(o[2 * dp + 1], ph, &vh4[2]);
                mma16816(o[2 * dp + 1], ph, &vl4[2]);
                mma16816(o[2 * dp + 1], pl, &vh4[2]);
            }
        }
        __syncthreads();
    }

    // epilogue: O/l -> bf16 hi/lo Y
    const float inv0 = 1.f / l0, inv1 = 1.f / l1;
    const int r0 = q0 + wid * 16 + (lid >> 2);
    const int cb = h * 128 + (lid & 3) * 2;
    #pragma unroll
    for (int dt = 0; dt < 16; dt++) {
        int c = cb + dt * 8;
        uint32_t lo;
        uint32_t hi = pack_split(o[dt][0] * inv0, o[dt][1] * inv0, lo);
        *(uint32_t*)(g_Yhi + (size_t)r0 * DIM + c) = hi;
        *(uint32_t*)(g_Ylo + (size_t)r0 * DIM + c) = lo;
        hi = pack_split(o[dt][2] * inv1, o[dt][3] * inv1, lo);
        *(uint32_t*)(g_Yhi + (size_t)(r0 + 8) * DIM + c) = hi;
        *(uint32_t*)(g_Ylo + (size_t)(r0 + 8) * DIM + c) = lo;
    }
}

// ---------------------------------------------------------------------------
// Launch
// ---------------------------------------------------------------------------
extern "C" void kernel_launch(void* const* d_in, const int* in_sizes, int n_in,
                              void* d_out, int out_size)
{
    (void)in_sizes; (void)n_in; (void)out_size;
    const float* x    = (const float*)d_in[0];
    const float* vi   = (const float*)d_in[1];
    const float* Wq   = (const float*)d_in[2];
    const float* Wk   = (const float*)d_in[3];
    const float* Wv   = (const float*)d_in[4];
    const float* Wp   = (const float*)d_in[5];
    const float* lamb = (const float*)d_in[6];
    float* out = (float*)d_out;

    float *Qp, *Kp, *Vp;
    __nv_bfloat16 *Xhi, *Xlo, *Yhi, *Ylo, *Whi, *Wlo;
    cudaGetSymbolAddress((void**)&Qp, g_Q);
    cudaGetSymbolAddress((void**)&Kp, g_K);
    cudaGetSymbolAddress((void**)&Vp, g_V);
    cudaGetSymbolAddress((void**)&Xhi, g_Xhi);
    cudaGetSymbolAddress((void**)&Xlo, g_Xlo);
    cudaGetSymbolAddress((void**)&Yhi, g_Yhi);
    cudaGetSymbolAddress((void**)&Ylo, g_Ylo);
    cudaGetSymbolAddress((void**)&Whi, g_Whi);
    cudaGetSymbolAddress((void**)&Wlo, g_Wlo);

    build_rope_tables<<<(SEQ * 64) / 256, 256>>>();

    split_bf16<<<(SEQ * DIM / 4) / 256, 256>>>((const float4*)x,
        (__nv_bfloat162*)Xhi, (__nv_bfloat162*)Xlo);
    const float* Ws[4] = {Wq, Wk, Wv, Wp};
    for (int w = 0; w < 4; w++) {
        split_bf16<<<(DIM * DIM / 4) / 256, 256>>>((const float4*)Ws[w],
            (__nv_bfloat162*)(Whi + (size_t)w * DIM * DIM),
            (__nv_bfloat162*)(Wlo + (size_t)w * DIM * DIM));
    }

    cudaFuncSetAttribute(gemm_mma<0>, cudaFuncAttributeMaxDynamicSharedMemorySize, GM_SMEM);
    cudaFuncSetAttribute(gemm_mma<1>, cudaFuncAttributeMaxDynamicSharedMemorySize, GM_SMEM);

    dim3 gg(DIM / 128, SEQ / 128);
    gemm_mma<0><<<gg, 256, GM_SMEM>>>(Xhi, Xlo,
        Whi + 0 * (size_t)DIM * DIM, Wlo + 0 * (size_t)DIM * DIM, Qp, nullptr, nullptr);
    gemm_mma<0><<<gg, 256, GM_SMEM>>>(Xhi, Xlo,
        Whi + 1 * (size_t)DIM * DIM, Wlo + 1 * (size_t)DIM * DIM, Kp, nullptr, nullptr);
    gemm_mma<1><<<gg, 256, GM_SMEM>>>(Xhi, Xlo,
        Whi + 2 * (size_t)DIM * DIM, Wlo + 2 * (size_t)DIM * DIM, Vp, vi, lamb);

    rmsnorm_rope_split<<<dim3(SEQ, NHEAD, 2), 128>>>();
    transpose_split_v<<<dim3(SEQ / 32, DIM / 32), dim3(32, 8)>>>();

    cudaFuncSetAttribute(flash_mma, cudaFuncAttributeMaxDynamicSharedMemorySize, FA_SMEM);
    flash_mma<<<dim3(SEQ / 128, NHEAD), 256, FA_SMEM>>>();

    gemm_mma<0><<<gg, 256, GM_SMEM>>>(Yhi, Ylo,
        Whi + 3 * (size_t)DIM * DIM, Wlo + 3 * (size_t)DIM * DIM, out, nullptr, nullptr);
}

// round 8
// speedup vs baseline: 3.3961x; 1.0018x over previous
#include <cuda_runtime.h>
#include <cuda_bf16.h>
#include <math.h>
#include <stdint.h>

#define SEQ   4096
#define DIM   2048
#define NHEAD 16
#define HDIM  128
#define EPSF  1.1920929e-07f
#define ATT_SCALE 0.08838834764831845f  // 128^-0.5

#define SW128(o) ((o) ^ (((o) >> 3) & 0x70))

// ---------------------------------------------------------------------------
// Scratch (device globals; no allocation allowed)
// ---------------------------------------------------------------------------
__device__ float g_Q[SEQ * DIM];
__device__ float g_K[SEQ * DIM];
__device__ float g_V[SEQ * DIM];
__device__ float g_cos[SEQ * (HDIM / 2)];
__device__ float g_sin[SEQ * (HDIM / 2)];
__device__ __nv_bfloat16 g_Xhi[SEQ * DIM];
__device__ __nv_bfloat16 g_Xlo[SEQ * DIM];
__device__ __nv_bfloat16 g_Yhi[SEQ * DIM];
__device__ __nv_bfloat16 g_Ylo[SEQ * DIM];
__device__ __nv_bfloat16 g_Whi[4 * DIM * DIM];
__device__ __nv_bfloat16 g_Wlo[4 * DIM * DIM];
// flash inputs (bf16 hi/lo)
__device__ __nv_bfloat16 g_Qh[SEQ * DIM];
__device__ __nv_bfloat16 g_Ql[SEQ * DIM];
__device__ __nv_bfloat16 g_Kh[SEQ * DIM];
__device__ __nv_bfloat16 g_Kl[SEQ * DIM];
__device__ __nv_bfloat16 g_Vth[DIM * SEQ];   // transposed: [dim][t]
__device__ __nv_bfloat16 g_Vtl[DIM * SEQ];

// ---------------------------------------------------------------------------
// PTX helpers (baseline sm_80+ only — harness target is plain sm_100)
// ---------------------------------------------------------------------------
__device__ __forceinline__ uint32_t smem_u32(const void* p) {
    uint32_t a;
    asm("{ .reg .u64 t; cvta.to.shared.u64 t, %1; cvt.u32.u64 %0, t; }"
        : "=r"(a) : "l"(p));
    return a;
}
__device__ __forceinline__ void cp16(uint32_t dst, const void* src) {
    asm volatile("cp.async.cg.shared.global [%0], [%1], 16;"
                 :: "r"(dst), "l"(src) : "memory");
}
__device__ __forceinline__ void cp_commit() {
    asm volatile("cp.async.commit_group;" ::: "memory");
}
template <int N>
__device__ __forceinline__ void cp_wait() {
    asm volatile("cp.async.wait_group %0;" :: "n"(N) : "memory");
}
__device__ __forceinline__ void ldsm4(uint32_t& r0, uint32_t& r1,
                                      uint32_t& r2, uint32_t& r3, uint32_t a) {
    asm volatile("ldmatrix.sync.aligned.m8n8.x4.shared.b16 {%0,%1,%2,%3}, [%4];"
                 : "=r"(r0), "=r"(r1), "=r"(r2), "=r"(r3) : "r"(a));
}
__device__ __forceinline__ void ldsm2(uint32_t& r0, uint32_t& r1, uint32_t a) {
    asm volatile("ldmatrix.sync.aligned.m8n8.x2.shared.b16 {%0,%1}, [%2];"
                 : "=r"(r0), "=r"(r1) : "r"(a));
}
__device__ __forceinline__ void mma16816(float* c, const uint32_t* a,
                                         const uint32_t* b) {
    asm volatile(
        "mma.sync.aligned.m16n8k16.row.col.f32.bf16.bf16.f32 "
        "{%0,%1,%2,%3}, {%4,%5,%6,%7}, {%8,%9}, {%0,%1,%2,%3};"
        : "+f"(c[0]), "+f"(c[1]), "+f"(c[2]), "+f"(c[3])
        : "r"(a[0]), "r"(a[1]), "r"(a[2]), "r"(a[3]), "r"(b[0]), "r"(b[1]));
}
// fast exp for x <= 0, rel err ~2.4e-6, FMA-pipe only (no MUFU)
__device__ __forceinline__ float fexp(float x) {
    float z = fmaxf(x * 1.4426950408889634f, -120.f);
    float n = rintf(z);
    float f = z - n;                       // [-0.5, 0.5]
    float p = fmaf(0.0013333558f, f, 0.0096181291f);
    p = fmaf(p, f, 0.0555041087f);
    p = fmaf(p, f, 0.2402265070f);
    p = fmaf(p, f, 0.6931471806f);
    p = fmaf(p, f, 1.0f);
    return p * __int_as_float(((int)n + 127) << 23);
}
__device__ __forceinline__ uint32_t pack_split(float a, float b, uint32_t& lo) {
    __nv_bfloat162 h = __floats2bfloat162_rn(a, b);
    __nv_bfloat162 l = __floats2bfloat162_rn(a - __bfloat162float(h.x),
                                             b - __bfloat162float(h.y));
    lo = *reinterpret_cast<uint32_t*>(&l);
    return *reinterpret_cast<uint32_t*>(&h);
}

// ---------------------------------------------------------------------------
// RoPE tables
// ---------------------------------------------------------------------------
__global__ void build_rope_tables()
{
    int idx = blockIdx.x * blockDim.x + threadIdx.x;
    int t = idx >> 6;
    int j = idx & 63;
    float invf = (float)pow(10000.0, -(double)j / 64.0);
    float ang = (float)t * invf;
    g_cos[idx] = (float)cos((double)ang);
    g_sin[idx] = (float)sin((double)ang);
}

// ---------------------------------------------------------------------------
// fp32 -> (bf16 hi, bf16 lo) split
// ---------------------------------------------------------------------------
__global__ void split_bf16(const float4* __restrict__ src,
                           __nv_bfloat162* __restrict__ hi,
                           __nv_bfloat162* __restrict__ lo)
{
    int i = blockIdx.x * blockDim.x + threadIdx.x;
    float4 v = src[i];
    uint32_t l0, l1;
    uint32_t h0 = pack_split(v.x, v.y, l0);
    uint32_t h1 = pack_split(v.z, v.w, l1);
    ((uint32_t*)hi)[2 * i] = h0; ((uint32_t*)hi)[2 * i + 1] = h1;
    ((uint32_t*)lo)[2 * i] = l0; ((uint32_t*)lo)[2 * i + 1] = l1;
}

// ---------------------------------------------------------------------------
// mma.sync GEMM (unchanged from R6): C = A*B^T, 3-term bf16 split.
// ---------------------------------------------------------------------------
#define OPND 16384
#define STAGE (4 * OPND)
#define GM_SMEM (2 * STAGE)

template <int MODE>
__global__ __launch_bounds__(256, 1)
void gemm_mma(const __nv_bfloat16* __restrict__ Ahi, const __nv_bfloat16* __restrict__ Alo,
              const __nv_bfloat16* __restrict__ Bhi, const __nv_bfloat16* __restrict__ Blo,
              float* __restrict__ C,
              const float* __restrict__ vi, const float* __restrict__ lambp)
{
    extern __shared__ char smc[];
    const uint32_t sb = smem_u32(smc);
    const int tid = threadIdx.x;
    const int wid = tid >> 5;
    const int lid = tid & 31;
    const int warp_m = wid & 1;
    const int warp_n = wid >> 1;
    const int m0 = blockIdx.y * 128;
    const int n0 = blockIdx.x * 128;

    const __nv_bfloat16* srcs[4] = { Ahi + (size_t)m0 * DIM, Alo + (size_t)m0 * DIM,
                                     Bhi + (size_t)n0 * DIM, Blo + (size_t)n0 * DIM };
    const int ldrow = tid >> 3;
    const int ldu   = tid & 7;

    auto load_chunk = [&](int chunk, int stage) {
        const int k0 = chunk * 64;
        #pragma unroll
        for (int t = 0; t < 4; t++) {
            const __nv_bfloat16* s = srcs[t] + k0 + ldu * 8;
            uint32_t dbase = sb + stage * STAGE + t * OPND;
            #pragma unroll
            for (int q = 0; q < 4; q++) {
                int row = ldrow + q * 32;
                cp16(dbase + SW128((uint32_t)(row * 128 + ldu * 16)),
                     s + (size_t)row * DIM);
            }
        }
        cp_commit();
    };

    float acc[4][4][4];
    #pragma unroll
    for (int a = 0; a < 4; a++)
        #pragma unroll
        for (int b = 0; b < 4; b++)
            #pragma unroll
            for (int c = 0; c < 4; c++) acc[a][b][c] = 0.f;

    const int aq = lid >> 3;
    const int a_row = warp_m * 64 + (aq & 1) * 8 + (lid & 7);
    const int a_ku  = aq >> 1;
    const int b_row = warp_n * 32 + (lid & 7);
    const int b_ku  = (lid >> 3) & 1;

    load_chunk(0, 0);

    for (int i = 0; i < 32; i++) {
        if (i + 1 < 32) { load_chunk(i + 1, (i + 1) & 1); cp_wait<1>(); }
        else            { cp_wait<0>(); }
        __syncthreads();

        const uint32_t st = sb + (i & 1) * STAGE;
        const uint32_t bAh = st, bAl = st + OPND, bBh = st + 2 * OPND, bBl = st + 3 * OPND;

        #pragma unroll
        for (int ks = 0; ks < 4; ks++) {
            uint32_t bh[8], bl[8];
            #pragma unroll
            for (int nt = 0; nt < 4; nt++) {
                uint32_t off = SW128((uint32_t)((b_row + nt * 8) * 128 + (ks * 2 + b_ku) * 16));
                ldsm2(bh[nt * 2], bh[nt * 2 + 1], bBh + off);
                ldsm2(bl[nt * 2], bl[nt * 2 + 1], bBl + off);
            }
            #pragma unroll
            for (int mt = 0; mt < 4; mt++) {
                uint32_t off = SW128((uint32_t)((a_row + mt * 16) * 128 + (ks * 2 + a_ku) * 16));
                uint32_t ah[4], al[4];
                ldsm4(ah[0], ah[1], ah[2], ah[3], bAh + off);
                ldsm4(al[0], al[1], al[2], al[3], bAl + off);
                #pragma unroll
                for (int nt = 0; nt < 4; nt++) {
                    mma16816(acc[mt][nt], ah, &bh[nt * 2]);
                    mma16816(acc[mt][nt], ah, &bl[nt * 2]);
                    mma16816(acc[mt][nt], al, &bh[nt * 2]);
                }
            }
        }
        __syncthreads();
    }

    float lam = 0.f, oml = 1.f;
    if (MODE == 1) { lam = *lambp; oml = 1.f - lam; }
    const int gid = lid >> 2;
    const int tg  = lid & 3;
    #pragma unroll
    for (int mt = 0; mt < 4; mt++) {
        #pragma unroll
        for (int nt = 0; nt < 4; nt++) {
            int r = m0 + warp_m * 64 + mt * 16 + gid;
            int c = n0 + warp_n * 32 + nt * 8 + tg * 2;
            float2 v01 = make_float2(acc[mt][nt][0], acc[mt][nt][1]);
            float2 v23 = make_float2(acc[mt][nt][2], acc[mt][nt][3]);
            if (MODE == 1) {
                float2 w0 = *(const float2*)(vi + (size_t)r * DIM + c);
                float2 w1 = *(const float2*)(vi + (size_t)(r + 8) * DIM + c);
                v01.x = oml * v01.x + lam * w0.x; v01.y = oml * v01.y + lam * w0.y;
                v23.x = oml * v23.x + lam * w1.x; v23.y = oml * v23.y + lam * w1.y;
            }
            *(float2*)(C + (size_t)r * DIM + c) = v01;
            *(float2*)(C + (size_t)(r + 8) * DIM + c) = v23;
        }
    }
}

// ---------------------------------------------------------------------------
// Fused RMSNorm + RoPE, fp32 in -> bf16 hi/lo out
// ---------------------------------------------------------------------------
__global__ void rmsnorm_rope_split()
{
    const int t = blockIdx.x;
    const int h = blockIdx.y;
    const int z = blockIdx.z;
    const float* row = (z == 0 ? g_Q : g_K) + t * 2048 + h * 128;
    __nv_bfloat16* oh = (z == 0 ? g_Qh : g_Kh) + t * 2048 + h * 128;
    __nv_bfloat16* ol = (z == 0 ? g_Ql : g_Kl) + t * 2048 + h * 128;
    const int i = threadIdx.x;

    float v = row[i];
    float ss = v * v;
    #pragma unroll
    for (int o = 16; o > 0; o >>= 1) ss += __shfl_xor_sync(0xffffffffu, ss, o);

    __shared__ float red[4];
    __shared__ float vals[128];
    if ((i & 31) == 0) red[i >> 5] = ss;
    __syncthreads();
    float tot = red[0] + red[1] + red[2] + red[3];
    vals[i] = v * rsqrtf(tot * (1.f / 128.f) + EPSF);
    __syncthreads();

    float out;
    if (i < 64) {
        out = vals[i] * g_cos[t * 64 + i] + vals[i + 64] * g_sin[t * 64 + i];
    } else {
        int j = i - 64;
        out = vals[i] * g_cos[t * 64 + j] - vals[i - 64] * g_sin[t * 64 + j];
    }
    __nv_bfloat16 hh = __float2bfloat16_rn(out);
    oh[i] = hh;
    ol[i] = __float2bfloat16_rn(out - __bfloat162float(hh));
}

// ---------------------------------------------------------------------------
// V fp32 [t][dim] -> transposed bf16 hi/lo [dim][t]
// ---------------------------------------------------------------------------
__global__ void transpose_split_v()
{
    __shared__ float tile[32][33];
    const int t0 = blockIdx.x * 32;
    const int d0 = blockIdx.y * 32;
    const int tx = threadIdx.x, ty = threadIdx.y;
    #pragma unroll
    for (int r = ty; r < 32; r += 8)
        tile[r][tx] = g_V[(size_t)(t0 + r) * DIM + d0 + tx];
    __syncthreads();
    #pragma unroll
    for (int r = ty; r < 32; r += 8) {
        float v = tile[tx][r];
        __nv_bfloat16 hh = __float2bfloat16_rn(v);
        size_t o = (size_t)(d0 + r) * SEQ + t0 + tx;
        g_Vth[o] = hh;
        g_Vtl[o] = __float2bfloat16_rn(v - __bfloat162float(hh));
    }
}

// ---------------------------------------------------------------------------
// Tensor-core causal flash attention.
// BM=128 q-rows x BN=64 keys, 8 warps (16 rows each), 3-term bf16 split for
// both S = Q K^T and O += P V. P stays in registers (C-frag == A-frag).
// smem: Qh/Ql [128][136] pad, Kh/Kl 2-stage [64][136], Vh/Vl 2-stage [128][72].
// ---------------------------------------------------------------------------
#define FA_SMEM 212992

__global__ __launch_bounds__(256, 1)
void flash_mma()
{
    extern __shared__ char fsm[];
    const uint32_t sb = smem_u32(fsm);
    const int tid = threadIdx.x;
    const int wid = tid >> 5;
    const int lid = tid & 31;
    const int qb  = (int)gridDim.x - 1 - (int)blockIdx.x;  // longest first
    const int h   = blockIdx.y;
    const int q0  = qb * 128;
    const int nkb = 2 * qb + 2;

    const uint32_t oQH = 0,      oQL = 34816;
    const uint32_t oKH = 69632,  oKL = 104448;   // + stage*17408
    const uint32_t oVH = 139264, oVL = 176128;   // + stage*18432

    const __nv_bfloat16* Qhg = g_Qh + (size_t)q0 * DIM + h * 128;
    const __nv_bfloat16* Qlg = g_Ql + (size_t)q0 * DIM + h * 128;

    // Q load (own commit group)
    #pragma unroll
    for (int q = 0; q < 8; q++) {
        int u = tid + q * 256;
        int row = u >> 4, cu = u & 15;
        cp16(sb + oQH + row * 272 + cu * 16, Qhg + (size_t)row * DIM + cu * 8);
        cp16(sb + oQL + row * 272 + cu * 16, Qlg + (size_t)row * DIM + cu * 8);
    }
    cp_commit();

    auto load_kv = [&](int kb, int st) {
        const int k0 = kb * 64;
        const __nv_bfloat16* kh = g_Kh + (size_t)k0 * DIM + h * 128;
        const __nv_bfloat16* kl = g_Kl + (size_t)k0 * DIM + h * 128;
        const uint32_t kdh = sb + oKH + st * 17408;
        const uint32_t kdl = sb + oKL + st * 17408;
        #pragma unroll
        for (int q = 0; q < 4; q++) {
            int u = tid + q * 256;
            int row = u >> 4, cu = u & 15;
            cp16(kdh + row * 272 + cu * 16, kh + (size_t)row * DIM + cu * 8);
            cp16(kdl + row * 272 + cu * 16, kl + (size_t)row * DIM + cu * 8);
        }
        const __nv_bfloat16* vh = g_Vth + (size_t)(h * 128) * SEQ + k0;
        const __nv_bfloat16* vl = g_Vtl + (size_t)(h * 128) * SEQ + k0;
        const uint32_t vdh = sb + oVH + st * 18432;
        const uint32_t vdl = sb + oVL + st * 18432;
        #pragma unroll
        for (int q = 0; q < 4; q++) {
            int u = tid + q * 256;
            int row = u >> 3, cu = u & 7;
            cp16(vdh + row * 144 + cu * 16, vh + (size_t)row * SEQ + cu * 8);
            cp16(vdl + row * 144 + cu * 16, vl + (size_t)row * SEQ + cu * 8);
        }
        cp_commit();
    };

    load_kv(0, 0);

    float m0r = -1e30f, m1r = -1e30f, l0 = 0.f, l1 = 0.f;
    float o[16][4];
    #pragma unroll
    for (int d = 0; d < 16; d++)
        #pragma unroll
        for (int j = 0; j < 4; j++) o[d][j] = 0.f;

    // fragment address components
    const int aq   = lid >> 3;
    const int arow = wid * 16 + (aq & 1) * 8 + (lid & 7);
    const int aku  = aq >> 1;
    const int brow = ((lid >> 4) << 3) + (lid & 7);  // nt_off*8 + lane row
    const int bku  = (lid >> 3) & 1;

    for (int kb = 0; kb < nkb; kb++) {
        if (kb + 1 < nkb) { load_kv(kb + 1, (kb + 1) & 1); cp_wait<1>(); }
        else              { cp_wait<0>(); }
        __syncthreads();

        const uint32_t kbh = sb + oKH + (kb & 1) * 17408;
        const uint32_t kbl = sb + oKL + (kb & 1) * 17408;
        const uint32_t vbh = sb + oVH + (kb & 1) * 18432;
        const uint32_t vbl = sb + oVL + (kb & 1) * 18432;

        // ---- S = Q K^T (16x64 per warp) ----
        float s[8][4];
        #pragma unroll
        for (int nt = 0; nt < 8; nt++)
            #pragma unroll
            for (int j = 0; j < 4; j++) s[nt][j] = 0.f;

        #pragma unroll
        for (int kt = 0; kt < 8; kt++) {
            uint32_t qh[4], ql[4];
            uint32_t qoff = (uint32_t)(arow * 272 + (kt * 2 + aku) * 16);
            ldsm4(qh[0], qh[1], qh[2], qh[3], sb + oQH + qoff);
            ldsm4(ql[0], ql[1], ql[2], ql[3], sb + oQL + qoff);
            #pragma unroll
            for (int np = 0; np < 4; np++) {
                uint32_t kh4[4], kl4[4];
                uint32_t koff = (uint32_t)((np * 16 + brow) * 272 + (kt * 2 + bku) * 16);
                ldsm4(kh4[0], kh4[1], kh4[2], kh4[3], kbh + koff);
                ldsm4(kl4[0], kl4[1], kl4[2], kl4[3], kbl + koff);
                mma16816(s[2 * np],     qh, &kh4[0]);
                mma16816(s[2 * np],     qh, &kl4[0]);
                mma16816(s[2 * np],     ql, &kh4[0]);
                mma16816(s[2 * np + 1], qh, &kh4[2]);
                mma16816(s[2 * np + 1], qh, &kl4[2]);
                mma16816(s[2 * np + 1], ql, &kh4[2]);
            }
        }

        // scale + causal mask
        #pragma unroll
        for (int nt = 0; nt < 8; nt++)
            #pragma unroll
            for (int j = 0; j < 4; j++) s[nt][j] *= ATT_SCALE;
        if (kb >= 2 * qb) {
            const int moff = (kb - 2 * qb) * 64;
            const int r0 = wid * 16 + (lid >> 2);
            #pragma unroll
            for (int nt = 0; nt < 8; nt++) {
                int c = nt * 8 + (lid & 3) * 2 + moff;
                if (c > r0)     s[nt][0] = -1e30f;
                if (c + 1 > r0) s[nt][1] = -1e30f;
                if (c > r0 + 8)     s[nt][2] = -1e30f;
                if (c + 1 > r0 + 8) s[nt][3] = -1e30f;
            }
        }

        // ---- online softmax (rows r0, r0+8 per thread; quad-lane reduce) ----
        float mx0 = -1e30f, mx1 = -1e30f;
        #pragma unroll
        for (int nt = 0; nt < 8; nt++) {
            mx0 = fmaxf(mx0, fmaxf(s[nt][0], s[nt][1]));
            mx1 = fmaxf(mx1, fmaxf(s[nt][2], s[nt][3]));
        }
        mx0 = fmaxf(mx0, __shfl_xor_sync(0xffffffffu, mx0, 1));
        mx0 = fmaxf(mx0, __shfl_xor_sync(0xffffffffu, mx0, 2));
        mx1 = fmaxf(mx1, __shfl_xor_sync(0xffffffffu, mx1, 1));
        mx1 = fmaxf(mx1, __shfl_xor_sync(0xffffffffu, mx1, 2));
        float nm0 = fmaxf(m0r, mx0), nm1 = fmaxf(m1r, mx1);
        float al0 = fexp(m0r - nm0), al1 = fexp(m1r - nm1);
        m0r = nm0; m1r = nm1;

        float rs0 = 0.f, rs1 = 0.f;
        #pragma unroll
        for (int nt = 0; nt < 8; nt++) {
            s[nt][0] = fexp(s[nt][0] - nm0);
            s[nt][1] = fexp(s[nt][1] - nm0);
            s[nt][2] = fexp(s[nt][2] - nm1);
            s[nt][3] = fexp(s[nt][3] - nm1);
            rs0 += s[nt][0] + s[nt][1];
            rs1 += s[nt][2] + s[nt][3];
        }
        rs0 += __shfl_xor_sync(0xffffffffu, rs0, 1);
        rs0 += __shfl_xor_sync(0xffffffffu, rs0, 2);
        rs1 += __shfl_xor_sync(0xffffffffu, rs1, 1);
        rs1 += __shfl_xor_sync(0xffffffffu, rs1, 2);
        l0 = l0 * al0 + rs0;
        l1 = l1 * al1 + rs1;
        #pragma unroll
        for (int d = 0; d < 16; d++) {
            o[d][0] *= al0; o[d][1] *= al0;
            o[d][2] *= al1; o[d][3] *= al1;
        }

        // ---- O += P V (P in registers as A-frags, hi/lo split) ----
        #pragma unroll
        for (int kt2 = 0; kt2 < 4; kt2++) {
            const int n0t = 2 * kt2, n1t = 2 * kt2 + 1;
            uint32_t ph[4], pl[4];
            ph[0] = pack_split(s[n0t][0], s[n0t][1], pl[0]);
            ph[1] = pack_split(s[n0t][2], s[n0t][3], pl[1]);
            ph[2] = pack_split(s[n1t][0], s[n1t][1], pl[2]);
            ph[3] = pack_split(s[n1t][2], s[n1t][3], pl[3]);
            #pragma unroll
            for (int dp = 0; dp < 8; dp++) {
                uint32_t vh4[4], vl4[4];
                uint32_t voff = (uint32_t)((dp * 16 + brow) * 144 + (kt2 * 2 + bku) * 16);
                ldsm4(vh4[0], vh4[1], vh4[2], vh4[3], vbh + voff);
                ldsm4(vl4[0], vl4[1], vl4[2], vl4[3], vbl + voff);
                mma16816(o[2 * dp],     ph, &vh4[0]);
                mma16816(o[2 * dp],     ph, &vl4[0]);
                mma16816(o[2 * dp],     pl, &vh4[0]);
                mma16816(o[2 * dp + 1], ph, &vh4[2]);
                mma16816(o[2 * dp + 1], ph, &vl4[2]);
                mma16816(o[2 * dp + 1], pl, &vh4[2]);
            }
        }
        __syncthreads();
    }

    // epilogue: O/l -> bf16 hi/lo Y
    const float inv0 = 1.f / l0, inv1 = 1.f / l1;
    const int r0 = q0 + wid * 16 + (lid >> 2);
    const int cb = h * 128 + (lid & 3) * 2;
    #pragma unroll
    for (int dt = 0; dt < 16; dt++) {
        int c = cb + dt * 8;
        uint32_t lo;
        uint32_t hi = pack_split(o[dt][0] * inv0, o[dt][1] * inv0, lo);
        *(uint32_t*)(g_Yhi + (size_t)r0 * DIM + c) = hi;
        *(uint32_t*)(g_Ylo + (size_t)r0 * DIM + c) = lo;
        hi = pack_split(o[dt][2] * inv1, o[dt][3] * inv1, lo);
        *(uint32_t*)(g_Yhi + (size_t)(r0 + 8) * DIM + c) = hi;
        *(uint32_t*)(g_Ylo + (size_t)(r0 + 8) * DIM + c) = lo;
    }
}

// ---------------------------------------------------------------------------
// Launch
// ---------------------------------------------------------------------------
extern "C" void kernel_launch(void* const* d_in, const int* in_sizes, int n_in,
                              void* d_out, int out_size)
{
    (void)in_sizes; (void)n_in; (void)out_size;
    const float* x    = (const float*)d_in[0];
    const float* vi   = (const float*)d_in[1];
    const float* Wq   = (const float*)d_in[2];
    const float* Wk   = (const float*)d_in[3];
    const float* Wv   = (const float*)d_in[4];
    const float* Wp   = (const float*)d_in[5];
    const float* lamb = (const float*)d_in[6];
    float* out = (float*)d_out;

    float *Qp, *Kp, *Vp;
    __nv_bfloat16 *Xhi, *Xlo, *Yhi, *Ylo, *Whi, *Wlo;
    cudaGetSymbolAddress((void**)&Qp, g_Q);
    cudaGetSymbolAddress((void**)&Kp, g_K);
    cudaGetSymbolAddress((void**)&Vp, g_V);
    cudaGetSymbolAddress((void**)&Xhi, g_Xhi);
    cudaGetSymbolAddress((void**)&Xlo, g_Xlo);
    cudaGetSymbolAddress((void**)&Yhi, g_Yhi);
    cudaGetSymbolAddress((void**)&Ylo, g_Ylo);
    cudaGetSymbolAddress((void**)&Whi, g_Whi);
    cudaGetSymbolAddress((void**)&Wlo, g_Wlo);

    build_rope_tables<<<(SEQ * 64) / 256, 256>>>();

    split_bf16<<<(SEQ * DIM / 4) / 256, 256>>>((const float4*)x,
        (__nv_bfloat162*)Xhi, (__nv_bfloat162*)Xlo);
    const float* Ws[4] = {Wq, Wk, Wv, Wp};
    for (int w = 0; w < 4; w++) {
        split_bf16<<<(DIM * DIM / 4) / 256, 256>>>((const float4*)Ws[w],
            (__nv_bfloat162*)(Whi + (size_t)w * DIM * DIM),
            (__nv_bfloat162*)(Wlo + (size_t)w * DIM * DIM));
    }

    cudaFuncSetAttribute(gemm_mma<0>, cudaFuncAttributeMaxDynamicSharedMemorySize, GM_SMEM);
    cudaFuncSetAttribute(gemm_mma<1>, cudaFuncAttributeMaxDynamicSharedMemorySize, GM_SMEM);

    dim3 gg(DIM / 128, SEQ / 128);
    gemm_mma<0><<<gg, 256, GM_SMEM>>>(Xhi, Xlo,
        Whi + 0 * (size_t)DIM * DIM, Wlo + 0 * (size_t)DIM * DIM, Qp, nullptr, nullptr);
    gemm_mma<0><<<gg, 256, GM_SMEM>>>(Xhi, Xlo,
        Whi + 1 * (size_t)DIM * DIM, Wlo + 1 * (size_t)DIM * DIM, Kp, nullptr, nullptr);
    gemm_mma<1><<<gg, 256, GM_SMEM>>>(Xhi, Xlo,
        Whi + 2 * (size_t)DIM * DIM, Wlo + 2 * (size_t)DIM * DIM, Vp, vi, lamb);

    rmsnorm_rope_split<<<dim3(SEQ, NHEAD, 2), 128>>>();
    transpose_split_v<<<dim3(SEQ / 32, DIM / 32), dim3(32, 8)>>>();

    cudaFuncSetAttribute(flash_mma, cudaFuncAttributeMaxDynamicSharedMemorySize, FA_SMEM);
    flash_mma<<<dim3(SEQ / 128, NHEAD), 256, FA_SMEM>>>();

    gemm_mma<0><<<gg, 256, GM_SMEM>>>(Yhi, Ylo,
        Whi + 3 * (size_t)DIM * DIM, Wlo + 3 * (size_t)DIM * DIM, out, nullptr, nullptr);
}

// round 9
// speedup vs baseline: 3.3995x; 1.0010x over previous
#include <cuda_runtime.h>
#include <cuda_bf16.h>
#include <math.h>
#include <stdint.h>

#define SEQ   4096
#define DIM   2048
#define NHEAD 16
#define HDIM  128
#define EPSF  1.1920929e-07f
#define ATT_SCALE 0.08838834764831845f  // 128^-0.5

#define SW128(o) ((o) ^ (((o) >> 3) & 0x70))

// ---------------------------------------------------------------------------
// Scratch (device globals; no allocation allowed)
// ---------------------------------------------------------------------------
__device__ float g_Q[SEQ * DIM];
__device__ float g_K[SEQ * DIM];
__device__ float g_V[SEQ * DIM];
__device__ float g_cos[SEQ * (HDIM / 2)];
__device__ float g_sin[SEQ * (HDIM / 2)];
__device__ __nv_bfloat16 g_Xhi[SEQ * DIM];
__device__ __nv_bfloat16 g_Xlo[SEQ * DIM];
__device__ __nv_bfloat16 g_Yhi[SEQ * DIM];
__device__ __nv_bfloat16 g_Ylo[SEQ * DIM];
__device__ __nv_bfloat16 g_Whi[4 * DIM * DIM];
__device__ __nv_bfloat16 g_Wlo[4 * DIM * DIM];
// flash inputs (bf16 hi/lo)
__device__ __nv_bfloat16 g_Qh[SEQ * DIM];
__device__ __nv_bfloat16 g_Ql[SEQ * DIM];
__device__ __nv_bfloat16 g_Kh[SEQ * DIM];
__device__ __nv_bfloat16 g_Kl[SEQ * DIM];
__device__ __nv_bfloat16 g_Vth[DIM * SEQ];   // transposed: [dim][t]
__device__ __nv_bfloat16 g_Vtl[DIM * SEQ];

// ---------------------------------------------------------------------------
// PTX helpers (baseline sm_80+ only — harness target is plain sm_100)
// ---------------------------------------------------------------------------
__device__ __forceinline__ uint32_t smem_u32(const void* p) {
    uint32_t a;
    asm("{ .reg .u64 t; cvta.to.shared.u64 t, %1; cvt.u32.u64 %0, t; }"
        : "=r"(a) : "l"(p));
    return a;
}
__device__ __forceinline__ void cp16(uint32_t dst, const void* src) {
    asm volatile("cp.async.cg.shared.global [%0], [%1], 16;"
                 :: "r"(dst), "l"(src) : "memory");
}
__device__ __forceinline__ void cp_commit() {
    asm volatile("cp.async.commit_group;" ::: "memory");
}
template <int N>
__device__ __forceinline__ void cp_wait() {
    asm volatile("cp.async.wait_group %0;" :: "n"(N) : "memory");
}
__device__ __forceinline__ void ldsm4(uint32_t& r0, uint32_t& r1,
                                      uint32_t& r2, uint32_t& r3, uint32_t a) {
    asm volatile("ldmatrix.sync.aligned.m8n8.x4.shared.b16 {%0,%1,%2,%3}, [%4];"
                 : "=r"(r0), "=r"(r1), "=r"(r2), "=r"(r3) : "r"(a));
}
__device__ __forceinline__ void ldsm2(uint32_t& r0, uint32_t& r1, uint32_t a) {
    asm volatile("ldmatrix.sync.aligned.m8n8.x2.shared.b16 {%0,%1}, [%2];"
                 : "=r"(r0), "=r"(r1) : "r"(a));
}
__device__ __forceinline__ void mma16816(float* c, const uint32_t* a,
                                         const uint32_t* b) {
    asm volatile(
        "mma.sync.aligned.m16n8k16.row.col.f32.bf16.bf16.f32 "
        "{%0,%1,%2,%3}, {%4,%5,%6,%7}, {%8,%9}, {%0,%1,%2,%3};"
        : "+f"(c[0]), "+f"(c[1]), "+f"(c[2]), "+f"(c[3])
        : "r"(a[0]), "r"(a[1]), "r"(a[2]), "r"(a[3]), "r"(b[0]), "r"(b[1]));
}
// fast exp for x <= 0, rel err ~2.4e-6, FMA-pipe only (no MUFU)
__device__ __forceinline__ float fexp(float x) {
    float z = fmaxf(x * 1.4426950408889634f, -120.f);
    float n = rintf(z);
    float f = z - n;                       // [-0.5, 0.5]
    float p = fmaf(0.0013333558f, f, 0.0096181291f);
    p = fmaf(p, f, 0.0555041087f);
    p = fmaf(p, f, 0.2402265070f);
    p = fmaf(p, f, 0.6931471806f);
    p = fmaf(p, f, 1.0f);
    return p * __int_as_float(((int)n + 127) << 23);
}
__device__ __forceinline__ uint32_t pack_split(float a, float b, uint32_t& lo) {
    __nv_bfloat162 h = __floats2bfloat162_rn(a, b);
    __nv_bfloat162 l = __floats2bfloat162_rn(a - __bfloat162float(h.x),
                                             b - __bfloat162float(h.y));
    lo = *reinterpret_cast<uint32_t*>(&l);
    return *reinterpret_cast<uint32_t*>(&h);
}

// ---------------------------------------------------------------------------
// RoPE tables
// ---------------------------------------------------------------------------
__global__ void build_rope_tables()
{
    int idx = blockIdx.x * blockDim.x + threadIdx.x;
    int t = idx >> 6;
    int j = idx & 63;
    float invf = (float)pow(10000.0, -(double)j / 64.0);
    float ang = (float)t * invf;
    g_cos[idx] = (float)cos((double)ang);
    g_sin[idx] = (float)sin((double)ang);
}

// ---------------------------------------------------------------------------
// fp32 -> (bf16 hi, bf16 lo) split
// ---------------------------------------------------------------------------
__global__ void split_bf16(const float4* __restrict__ src,
                           __nv_bfloat162* __restrict__ hi,
                           __nv_bfloat162* __restrict__ lo)
{
    int i = blockIdx.x * blockDim.x + threadIdx.x;
    float4 v = src[i];
    uint32_t l0, l1;
    uint32_t h0 = pack_split(v.x, v.y, l0);
    uint32_t h1 = pack_split(v.z, v.w, l1);
    ((uint32_t*)hi)[2 * i] = h0; ((uint32_t*)hi)[2 * i + 1] = h1;
    ((uint32_t*)lo)[2 * i] = l0; ((uint32_t*)lo)[2 * i + 1] = l1;
}

// ---------------------------------------------------------------------------
// mma.sync GEMM (unchanged from R6): C = A*B^T, 3-term bf16 split.
// ---------------------------------------------------------------------------
#define OPND 16384
#define STAGE (4 * OPND)
#define GM_SMEM (2 * STAGE)

template <int MODE>
__global__ __launch_bounds__(256, 1)
void gemm_mma(const __nv_bfloat16* __restrict__ Ahi, const __nv_bfloat16* __restrict__ Alo,
              const __nv_bfloat16* __restrict__ Bhi, const __nv_bfloat16* __restrict__ Blo,
              float* __restrict__ C,
              const float* __restrict__ vi, const float* __restrict__ lambp)
{
    extern __shared__ char smc[];
    const uint32_t sb = smem_u32(smc);
    const int tid = threadIdx.x;
    const int wid = tid >> 5;
    const int lid = tid & 31;
    const int warp_m = wid & 1;
    const int warp_n = wid >> 1;
    const int m0 = blockIdx.y * 128;
    const int n0 = blockIdx.x * 128;

    const __nv_bfloat16* srcs[4] = { Ahi + (size_t)m0 * DIM, Alo + (size_t)m0 * DIM,
                                     Bhi + (size_t)n0 * DIM, Blo + (size_t)n0 * DIM };
    const int ldrow = tid >> 3;
    const int ldu   = tid & 7;

    auto load_chunk = [&](int chunk, int stage) {
        const int k0 = chunk * 64;
        #pragma unroll
        for (int t = 0; t < 4; t++) {
            const __nv_bfloat16* s = srcs[t] + k0 + ldu * 8;
            uint32_t dbase = sb + stage * STAGE + t * OPND;
            #pragma unroll
            for (int q = 0; q < 4; q++) {
                int row = ldrow + q * 32;
                cp16(dbase + SW128((uint32_t)(row * 128 + ldu * 16)),
                     s + (size_t)row * DIM);
            }
        }
        cp_commit();
    };

    float acc[4][4][4];
    #pragma unroll
    for (int a = 0; a < 4; a++)
        #pragma unroll
        for (int b = 0; b < 4; b++)
            #pragma unroll
            for (int c = 0; c < 4; c++) acc[a][b][c] = 0.f;

    const int aq = lid >> 3;
    const int a_row = warp_m * 64 + (aq & 1) * 8 + (lid & 7);
    const int a_ku  = aq >> 1;
    const int b_row = warp_n * 32 + (lid & 7);
    const int b_ku  = (lid >> 3) & 1;

    load_chunk(0, 0);

    for (int i = 0; i < 32; i++) {
        if (i + 1 < 32) { load_chunk(i + 1, (i + 1) & 1); cp_wait<1>(); }
        else            { cp_wait<0>(); }
        __syncthreads();

        const uint32_t st = sb + (i & 1) * STAGE;
        const uint32_t bAh = st, bAl = st + OPND, bBh = st + 2 * OPND, bBl = st + 3 * OPND;

        #pragma unroll
        for (int ks = 0; ks < 4; ks++) {
            uint32_t bh[8], bl[8];
            #pragma unroll
            for (int nt = 0; nt < 4; nt++) {
                uint32_t off = SW128((uint32_t)((b_row + nt * 8) * 128 + (ks * 2 + b_ku) * 16));
                ldsm2(bh[nt * 2], bh[nt * 2 + 1], bBh + off);
                ldsm2(bl[nt * 2], bl[nt * 2 + 1], bBl + off);
            }
            #pragma unroll
            for (int mt = 0; mt < 4; mt++) {
                uint32_t off = SW128((uint32_t)((a_row + mt * 16) * 128 + (ks * 2 + a_ku) * 16));
                uint32_t ah[4], al[4];
                ldsm4(ah[0], ah[1], ah[2], ah[3], bAh + off);
                ldsm4(al[0], al[1], al[2], al[3], bAl + off);
                #pragma unroll
                for (int nt = 0; nt < 4; nt++) {
                    mma16816(acc[mt][nt], ah, &bh[nt * 2]);
                    mma16816(acc[mt][nt], ah, &bl[nt * 2]);
                    mma16816(acc[mt][nt], al, &bh[nt * 2]);
                }
            }
        }
        __syncthreads();
    }

    float lam = 0.f, oml = 1.f;
    if (MODE == 1) { lam = *lambp; oml = 1.f - lam; }
    const int gid = lid >> 2;
    const int tg  = lid & 3;
    #pragma unroll
    for (int mt = 0; mt < 4; mt++) {
        #pragma unroll
        for (int nt = 0; nt < 4; nt++) {
            int r = m0 + warp_m * 64 + mt * 16 + gid;
            int c = n0 + warp_n * 32 + nt * 8 + tg * 2;
            float2 v01 = make_float2(acc[mt][nt][0], acc[mt][nt][1]);
            float2 v23 = make_float2(acc[mt][nt][2], acc[mt][nt][3]);
            if (MODE == 1) {
                float2 w0 = *(const float2*)(vi + (size_t)r * DIM + c);
                float2 w1 = *(const float2*)(vi + (size_t)(r + 8) * DIM + c);
                v01.x = oml * v01.x + lam * w0.x; v01.y = oml * v01.y + lam * w0.y;
                v23.x = oml * v23.x + lam * w1.x; v23.y = oml * v23.y + lam * w1.y;
            }
            *(float2*)(C + (size_t)r * DIM + c) = v01;
            *(float2*)(C + (size_t)(r + 8) * DIM + c) = v23;
        }
    }
}

// ---------------------------------------------------------------------------
// Fused RMSNorm + RoPE, fp32 in -> bf16 hi/lo out
// ---------------------------------------------------------------------------
__global__ void rmsnorm_rope_split()
{
    const int t = blockIdx.x;
    const int h = blockIdx.y;
    const int z = blockIdx.z;
    const float* row = (z == 0 ? g_Q : g_K) + t * 2048 + h * 128;
    __nv_bfloat16* oh = (z == 0 ? g_Qh : g_Kh) + t * 2048 + h * 128;
    __nv_bfloat16* ol = (z == 0 ? g_Ql : g_Kl) + t * 2048 + h * 128;
    const int i = threadIdx.x;

    float v = row[i];
    float ss = v * v;
    #pragma unroll
    for (int o = 16; o > 0; o >>= 1) ss += __shfl_xor_sync(0xffffffffu, ss, o);

    __shared__ float red[4];
    __shared__ float vals[128];
    if ((i & 31) == 0) red[i >> 5] = ss;
    __syncthreads();
    float tot = red[0] + red[1] + red[2] + red[3];
    vals[i] = v * rsqrtf(tot * (1.f / 128.f) + EPSF);
    __syncthreads();

    float out;
    if (i < 64) {
        out = vals[i] * g_cos[t * 64 + i] + vals[i + 64] * g_sin[t * 64 + i];
    } else {
        int j = i - 64;
        out = vals[i] * g_cos[t * 64 + j] - vals[i - 64] * g_sin[t * 64 + j];
    }
    __nv_bfloat16 hh = __float2bfloat16_rn(out);
    oh[i] = hh;
    ol[i] = __float2bfloat16_rn(out - __bfloat162float(hh));
}

// ---------------------------------------------------------------------------
// V fp32 [t][dim] -> transposed bf16 hi/lo [dim][t]
// ---------------------------------------------------------------------------
__global__ void transpose_split_v()
{
    __shared__ float tile[32][33];
    const int t0 = blockIdx.x * 32;
    const int d0 = blockIdx.y * 32;
    const int tx = threadIdx.x, ty = threadIdx.y;
    #pragma unroll
    for (int r = ty; r < 32; r += 8)
        tile[r][tx] = g_V[(size_t)(t0 + r) * DIM + d0 + tx];
    __syncthreads();
    #pragma unroll
    for (int r = ty; r < 32; r += 8) {
        float v = tile[tx][r];
        __nv_bfloat16 hh = __float2bfloat16_rn(v);
        size_t o = (size_t)(d0 + r) * SEQ + t0 + tx;
        g_Vth[o] = hh;
        g_Vtl[o] = __float2bfloat16_rn(v - __bfloat162float(hh));
    }
}

// ---------------------------------------------------------------------------
// Tensor-core causal flash attention.
// BM=128 q-rows x BN=64 keys, 8 warps (16 rows each), 3-term bf16 split for
// both S = Q K^T and O += P V. P stays in registers (C-frag == A-frag).
// smem: Qh/Ql [128][136] pad, Kh/Kl 2-stage [64][136], Vh/Vl 2-stage [128][72].
// ---------------------------------------------------------------------------
#define FA_SMEM 212992

__global__ __launch_bounds__(256, 1)
void flash_mma()
{
    extern __shared__ char fsm[];
    const uint32_t sb = smem_u32(fsm);
    const int tid = threadIdx.x;
    const int wid = tid >> 5;
    const int lid = tid & 31;
    const int qb  = (int)gridDim.x - 1 - (int)blockIdx.x;  // longest first
    const int h   = blockIdx.y;
    const int q0  = qb * 128;
    const int nkb = 2 * qb + 2;

    const uint32_t oQH = 0,      oQL = 34816;
    const uint32_t oKH = 69632,  oKL = 104448;   // + stage*17408
    const uint32_t oVH = 139264, oVL = 176128;   // + stage*18432

    const __nv_bfloat16* Qhg = g_Qh + (size_t)q0 * DIM + h * 128;
    const __nv_bfloat16* Qlg = g_Ql + (size_t)q0 * DIM + h * 128;

    // Q load (own commit group)
    #pragma unroll
    for (int q = 0; q < 8; q++) {
        int u = tid + q * 256;
        int row = u >> 4, cu = u & 15;
        cp16(sb + oQH + row * 272 + cu * 16, Qhg + (size_t)row * DIM + cu * 8);
        cp16(sb + oQL + row * 272 + cu * 16, Qlg + (size_t)row * DIM + cu * 8);
    }
    cp_commit();

    auto load_kv = [&](int kb, int st) {
        const int k0 = kb * 64;
        const __nv_bfloat16* kh = g_Kh + (size_t)k0 * DIM + h * 128;
        const __nv_bfloat16* kl = g_Kl + (size_t)k0 * DIM + h * 128;
        const uint32_t kdh = sb + oKH + st * 17408;
        const uint32_t kdl = sb + oKL + st * 17408;
        #pragma unroll
        for (int q = 0; q < 4; q++) {
            int u = tid + q * 256;
            int row = u >> 4, cu = u & 15;
            cp16(kdh + row * 272 + cu * 16, kh + (size_t)row * DIM + cu * 8);
            cp16(kdl + row * 272 + cu * 16, kl + (size_t)row * DIM + cu * 8);
        }
        const __nv_bfloat16* vh = g_Vth + (size_t)(h * 128) * SEQ + k0;
        const __nv_bfloat16* vl = g_Vtl + (size_t)(h * 128) * SEQ + k0;
        const uint32_t vdh = sb + oVH + st * 18432;
        const uint32_t vdl = sb + oVL + st * 18432;
        #pragma unroll
        for (int q = 0; q < 4; q++) {
            int u = tid + q * 256;
            int row = u >> 3, cu = u & 7;
            cp16(vdh + row * 144 + cu * 16, vh + (size_t)row * SEQ + cu * 8);
            cp16(vdl + row * 144 + cu * 16, vl + (size_t)row * SEQ + cu * 8);
        }
        cp_commit();
    };

    load_kv(0, 0);

    float m0r = -1e30f, m1r = -1e30f, l0 = 0.f, l1 = 0.f;
    float o[16][4];
    #pragma unroll
    for (int d = 0; d < 16; d++)
        #pragma unroll
        for (int j = 0; j < 4; j++) o[d][j] = 0.f;

    // fragment address components
    const int aq   = lid >> 3;
    const int arow = wid * 16 + (aq & 1) * 8 + (lid & 7);
    const int aku  = aq >> 1;
    const int brow = ((lid >> 4) << 3) + (lid & 7);  // nt_off*8 + lane row
    const int bku  = (lid >> 3) & 1;

    for (int kb = 0; kb < nkb; kb++) {
        if (kb + 1 < nkb) { load_kv(kb + 1, (kb + 1) & 1); cp_wait<1>(); }
        else              { cp_wait<0>(); }
        __syncthreads();

        const uint32_t kbh = sb + oKH + (kb & 1) * 17408;
        const uint32_t kbl = sb + oKL + (kb & 1) * 17408;
        const uint32_t vbh = sb + oVH + (kb & 1) * 18432;
        const uint32_t vbl = sb + oVL + (kb & 1) * 18432;

        // ---- S = Q K^T (16x64 per warp) ----
        float s[8][4];
        #pragma unroll
        for (int nt = 0; nt < 8; nt++)
            #pragma unroll
            for (int j = 0; j < 4; j++) s[nt][j] = 0.f;

        #pragma unroll
        for (int kt = 0; kt < 8; kt++) {
            uint32_t qh[4], ql[4];
            uint32_t qoff = (uint32_t)(arow * 272 + (kt * 2 + aku) * 16);
            ldsm4(qh[0], qh[1], qh[2], qh[3], sb + oQH + qoff);
            ldsm4(ql[0], ql[1], ql[2], ql[3], sb + oQL + qoff);
            #pragma unroll
            for (int np = 0; np < 4; np++) {
                uint32_t kh4[4], kl4[4];
                uint32_t koff = (uint32_t)((np * 16 + brow) * 272 + (kt * 2 + bku) * 16);
                ldsm4(kh4[0], kh4[1], kh4[2], kh4[3], kbh + koff);
                ldsm4(kl4[0], kl4[1], kl4[2], kl4[3], kbl + koff);
                mma16816(s[2 * np],     qh, &kh4[0]);
                mma16816(s[2 * np],     qh, &kl4[0]);
                mma16816(s[2 * np],     ql, &kh4[0]);
                mma16816(s[2 * np + 1], qh, &kh4[2]);
                mma16816(s[2 * np + 1], qh, &kl4[2]);
                mma16816(s[2 * np + 1], ql, &kh4[2]);
            }
        }

        // scale + causal mask
        #pragma unroll
        for (int nt = 0; nt < 8; nt++)
            #pragma unroll
            for (int j = 0; j < 4; j++) s[nt][j] *= ATT_SCALE;
        if (kb >= 2 * qb) {
            const int moff = (kb - 2 * qb) * 64;
            const int r0 = wid * 16 + (lid >> 2);
            #pragma unroll
            for (int nt = 0; nt < 8; nt++) {
                int c = nt * 8 + (lid & 3) * 2 + moff;
                if (c > r0)     s[nt][0] = -1e30f;
                if (c + 1 > r0) s[nt][1] = -1e30f;
                if (c > r0 + 8)     s[nt][2] = -1e30f;
                if (c + 1 > r0 + 8) s[nt][3] = -1e30f;
            }
        }

        // ---- online softmax (rows r0, r0+8 per thread; quad-lane reduce) ----
        float mx0 = -1e30f, mx1 = -1e30f;
        #pragma unroll
        for (int nt = 0; nt < 8; nt++) {
            mx0 = fmaxf(mx0, fmaxf(s[nt][0], s[nt][1]));
            mx1 = fmaxf(mx1, fmaxf(s[nt][2], s[nt][3]));
        }
        mx0 = fmaxf(mx0, __shfl_xor_sync(0xffffffffu, mx0, 1));
        mx0 = fmaxf(mx0, __shfl_xor_sync(0xffffffffu, mx0, 2));
        mx1 = fmaxf(mx1, __shfl_xor_sync(0xffffffffu, mx1, 1));
        mx1 = fmaxf(mx1, __shfl_xor_sync(0xffffffffu, mx1, 2));
        float nm0 = fmaxf(m0r, mx0), nm1 = fmaxf(m1r, mx1);
        float al0 = fexp(m0r - nm0), al1 = fexp(m1r - nm1);
        m0r = nm0; m1r = nm1;

        float rs0 = 0.f, rs1 = 0.f;
        #pragma unroll
        for (int nt = 0; nt < 8; nt++) {
            s[nt][0] = fexp(s[nt][0] - nm0);
            s[nt][1] = fexp(s[nt][1] - nm0);
            s[nt][2] = fexp(s[nt][2] - nm1);
            s[nt][3] = fexp(s[nt][3] - nm1);
            rs0 += s[nt][0] + s[nt][1];
            rs1 += s[nt][2] + s[nt][3];
        }
        rs0 += __shfl_xor_sync(0xffffffffu, rs0, 1);
        rs0 += __shfl_xor_sync(0xffffffffu, rs0, 2);
        rs1 += __shfl_xor_sync(0xffffffffu, rs1, 1);
        rs1 += __shfl_xor_sync(0xffffffffu, rs1, 2);
        l0 = l0 * al0 + rs0;
        l1 = l1 * al1 + rs1;
        #pragma unroll
        for (int d = 0; d < 16; d++) {
            o[d][0] *= al0; o[d][1] *= al0;
            o[d][2] *= al1; o[d][3] *= al1;
        }

        // ---- O += P V (P in registers as A-frags, hi/lo split) ----
        #pragma unroll
        for (int kt2 = 0; kt2 < 4; kt2++) {
            const int n0t = 2 * kt2, n1t = 2 * kt2 + 1;
            uint32_t ph[4], pl[4];
            ph[0] = pack_split(s[n0t][0], s[n0t][1], pl[0]);
            ph[1] = pack_split(s[n0t][2], s[n0t][3], pl[1]);
            ph[2] = pack_split(s[n1t][0], s[n1t][1], pl[2]);
            ph[3] = pack_split(s[n1t][2], s[n1t][3], pl[3]);
            #pragma unroll
            for (int dp = 0; dp < 8; dp++) {
                uint32_t vh4[4], vl4[4];
                uint32_t voff = (uint32_t)((dp * 16 + brow) * 144 + (kt2 * 2 + bku) * 16);
                ldsm4(vh4[0], vh4[1], vh4[2], vh4[3], vbh + voff);
                ldsm4(vl4[0], vl4[1], vl4[2], vl4[3], vbl + voff);
                mma16816(o[2 * dp],     ph, &vh4[0]);
                mma16816(o[2 * dp],     ph, &vl4[0]);
                mma16816(o[2 * dp],     pl, &vh4[0]);
                mma16816(o[2 * dp + 1], ph, &vh4[2]);
                mma16816(o[2 * dp + 1], ph, &vl4[2]);
                mma16816(o[2 * dp + 1], pl, &vh4[2]);
            }
        }
        __syncthreads();
    }

    // epilogue: O/l -> bf16 hi/lo Y
    const float inv0 = 1.f / l0, inv1 = 1.f / l1;
    const int r0 = q0 + wid * 16 + (lid >> 2);
    const int cb = h * 128 + (lid & 3) * 2;
    #pragma unroll
    for (int dt = 0; dt < 16; dt++) {
        int c = cb + dt * 8;
        uint32_t lo;
        uint32_t hi = pack_split(o[dt][0] * inv0, o[dt][1] * inv0, lo);
        *(uint32_t*)(g_Yhi + (size_t)r0 * DIM + c) = hi;
        *(uint32_t*)(g_Ylo + (size_t)r0 * DIM + c) = lo;
        hi = pack_split(o[dt][2] * inv1, o[dt][3] * inv1, lo);
        *(uint32_t*)(g_Yhi + (size_t)(r0 + 8) * DIM + c) = hi;
        *(uint32_t*)(g_Ylo + (size_t)(r0 + 8) * DIM + c) = lo;
    }
}

// ---------------------------------------------------------------------------
// Launch
// ---------------------------------------------------------------------------
extern "C" void kernel_launch(void* const* d_in, const int* in_sizes, int n_in,
                              void* d_out, int out_size)
{
    (void)in_sizes; (void)n_in; (void)out_size;
    const float* x    = (const float*)d_in[0];
    const float* vi   = (const float*)d_in[1];
    const float* Wq   = (const float*)d_in[2];
    const float* Wk   = (const float*)d_in[3];
    const float* Wv   = (const float*)d_in[4];
    const float* Wp   = (const float*)d_in[5];
    const float* lamb = (const float*)d_in[6];
    float* out = (float*)d_out;

    float *Qp, *Kp, *Vp;
    __nv_bfloat16 *Xhi, *Xlo, *Yhi, *Ylo, *Whi, *Wlo;
    cudaGetSymbolAddress((void**)&Qp, g_Q);
    cudaGetSymbolAddress((void**)&Kp, g_K);
    cudaGetSymbolAddress((void**)&Vp, g_V);
    cudaGetSymbolAddress((void**)&Xhi, g_Xhi);
    cudaGetSymbolAddress((void**)&Xlo, g_Xlo);
    cudaGetSymbolAddress((void**)&Yhi, g_Yhi);
    cudaGetSymbolAddress((void**)&Ylo, g_Ylo);
    cudaGetSymbolAddress((void**)&Whi, g_Whi);
    cudaGetSymbolAddress((void**)&Wlo, g_Wlo);

    build_rope_tables<<<(SEQ * 64) / 256, 256>>>();

    split_bf16<<<(SEQ * DIM / 4) / 256, 256>>>((const float4*)x,
        (__nv_bfloat162*)Xhi, (__nv_bfloat162*)Xlo);
    const float* Ws[4] = {Wq, Wk, Wv, Wp};
    for (int w = 0; w < 4; w++) {
        split_bf16<<<(DIM * DIM / 4) / 256, 256>>>((const float4*)Ws[w],
            (__nv_bfloat162*)(Whi + (size_t)w * DIM * DIM),
            (__nv_bfloat162*)(Wlo + (size_t)w * DIM * DIM));
    }

    cudaFuncSetAttribute(gemm_mma<0>, cudaFuncAttributeMaxDynamicSharedMemorySize, GM_SMEM);
    cudaFuncSetAttribute(gemm_mma<1>, cudaFuncAttributeMaxDynamicSharedMemorySize, GM_SMEM);

    dim3 gg(DIM / 128, SEQ / 128);
    gemm_mma<0><<<gg, 256, GM_SMEM>>>(Xhi, Xlo,
        Whi + 0 * (size_t)DIM * DIM, Wlo + 0 * (size_t)DIM * DIM, Qp, nullptr, nullptr);
    gemm_mma<0><<<gg, 256, GM_SMEM>>>(Xhi, Xlo,
        Whi + 1 * (size_t)DIM * DIM, Wlo + 1 * (size_t)DIM * DIM, Kp, nullptr, nullptr);
    gemm_mma<1><<<gg, 256, GM_SMEM>>>(Xhi, Xlo,
        Whi + 2 * (size_t)DIM * DIM, Wlo + 2 * (size_t)DIM * DIM, Vp, vi, lamb);

    rmsnorm_rope_split<<<dim3(SEQ, NHEAD, 2), 128>>>();
    transpose_split_v<<<dim3(SEQ / 32, DIM / 32), dim3(32, 8)>>>();

    cudaFuncSetAttribute(flash_mma, cudaFuncAttributeMaxDynamicSharedMemorySize, FA_SMEM);
    flash_mma<<<dim3(SEQ / 128, NHEAD), 256, FA_SMEM>>>();

    gemm_mma<0><<<gg, 256, GM_SMEM>>>(Yhi, Ylo,
        Whi + 3 * (size_t)DIM * DIM, Wlo + 3 * (size_t)DIM * DIM, out, nullptr, nullptr);
}